// round 6
// baseline (speedup 1.0000x reference)
#include <cuda_runtime.h>

#define HIDDEN 1024
#define HEADS 16
#define HDIM 64
#define BATCH 2
#define SEQ 2048
#define MROWS (BATCH * SEQ)   // 4096

// ---------------- scratch (device globals; allocation-free) ----------------
__device__ float g_Q[(size_t)BATCH * HEADS * SEQ * HDIM];
__device__ float g_K[(size_t)BATCH * HEADS * SEQ * HDIM];
__device__ float g_V[(size_t)BATCH * HEADS * SEQ * HDIM];
__device__ float g_att[(size_t)BATCH * SEQ * HIDDEN];

// ---------------- fp32 tiled GEMM:  C[m,n] = sum_k A[m,k]*B[n,k] + bias[n] --
// MODE 1: A = x, epilogue scatters into g_Q/g_K/g_V ([b,h,s,d] layout)
// MODE 2: A = g_att (internal), epilogue writes plain row-major C
template <int MODE>
__global__ __launch_bounds__(256, 2) void sgemm_kernel(
    const float* __restrict__ A, const float* __restrict__ B,
    const float* __restrict__ bias, float* __restrict__ C,
    int N, int K)
{
    constexpr int BM = 128, BN = 128, BK = 16;
    __shared__ __align__(16) float As[BK][BM + 4];
    __shared__ __align__(16) float Bs[BK][BN + 4];

    const int tid = threadIdx.x;
    const int tr = tid >> 4;     // 0..15
    const int tc = tid & 15;     // 0..15

    const float* Ab = (MODE == 2 ? g_att : A) + (size_t)blockIdx.y * BM * K;
    const float* Bb = B + (size_t)blockIdx.x * BN * K;

    float acc[8][8];
#pragma unroll
    for (int i = 0; i < 8; i++)
#pragma unroll
        for (int j = 0; j < 8; j++) acc[i][j] = 0.0f;

    for (int k0 = 0; k0 < K; k0 += BK) {
#pragma unroll
        for (int t = 0; t < 2; t++) {
            int v = tid + t * 256;        // 0..511 float4 slots
            int row = v >> 2;             // 0..127
            int c4 = (v & 3) << 2;        // 0,4,8,12
            float4 av = *(const float4*)(Ab + (size_t)row * K + k0 + c4);
            As[c4 + 0][row] = av.x; As[c4 + 1][row] = av.y;
            As[c4 + 2][row] = av.z; As[c4 + 3][row] = av.w;
            float4 bv = *(const float4*)(Bb + (size_t)row * K + k0 + c4);
            Bs[c4 + 0][row] = bv.x; Bs[c4 + 1][row] = bv.y;
            Bs[c4 + 2][row] = bv.z; Bs[c4 + 3][row] = bv.w;
        }
        __syncthreads();

#pragma unroll
        for (int kk = 0; kk < BK; kk++) {
            float4 a0 = *(const float4*)&As[kk][tr * 8];
            float4 a1 = *(const float4*)&As[kk][tr * 8 + 4];
            float4 b0 = *(const float4*)&Bs[kk][tc * 8];
            float4 b1 = *(const float4*)&Bs[kk][tc * 8 + 4];
            float a[8] = {a0.x, a0.y, a0.z, a0.w, a1.x, a1.y, a1.z, a1.w};
            float bb[8] = {b0.x, b0.y, b0.z, b0.w, b1.x, b1.y, b1.z, b1.w};
#pragma unroll
            for (int i = 0; i < 8; i++)
#pragma unroll
                for (int j = 0; j < 8; j++)
                    acc[i][j] = fmaf(a[i], bb[j], acc[i][j]);
        }
        __syncthreads();
    }

#pragma unroll
    for (int i = 0; i < 8; i++) {
        int m = blockIdx.y * BM + tr * 8 + i;
#pragma unroll
        for (int j = 0; j < 8; j++) {
            int n = blockIdx.x * BN + tc * 8 + j;
            float val = acc[i][j] + bias[n];
            if (MODE == 1) {
                // n -> (head, q/k/v, dim): head = n/192, jj = n%192
                int b = m >> 11;            // SEQ = 2048
                int s = m & (SEQ - 1);
                int h = n / 192;
                int jj = n - h * 192;
                float* dst = (jj < 64) ? g_Q : (jj < 128 ? g_K : g_V);
                dst[((((size_t)b * HEADS + h) * SEQ + s) << 6) + (jj & 63)] = val;
            } else {
                C[(size_t)m * N + n] = val;
            }
        }
    }
}

// ---------------- flash attention (fp32, online softmax) -------------------
// One CTA per (b, h, 64-row query block). 256 threads, 4x4 fragments.
// smem: Qs [d][q] (transposed), KVs: K as [d][key] / V as [seq][d], Ps [key][q]
#define PADS 68
#define ATTN_SMEM (3 * 64 * PADS * (int)sizeof(float))

__global__ __launch_bounds__(256, 2) void attn_kernel()
{
    extern __shared__ __align__(16) float sm[];
    float* Qs  = sm;
    float* KVs = sm + 64 * PADS;
    float* Ps  = sm + 2 * 64 * PADS;

    const int tid = threadIdx.x;
    const int tr = tid >> 4;   // query-row group 0..15
    const int tc = tid & 15;   // key/dim-col group 0..15
    const int qb = blockIdx.x;
    const int h  = blockIdx.y;
    const int b  = blockIdx.z;

    const size_t headBase = ((size_t)b * HEADS + h) * SEQ * HDIM;
    const float* Qg = g_Q + headBase + (size_t)qb * 64 * HDIM;
    const float* Kg = g_K + headBase;
    const float* Vg = g_V + headBase;

    // load Q transposed and pre-scaled by 1/sqrt(Dh) = 0.125
#pragma unroll
    for (int t = 0; t < 4; t++) {
        int v = tid + t * 256;            // 0..1023 float4 slots
        int r  = v >> 4;                  // query row 0..63
        int d0 = (v & 15) << 2;           // dim 0..60
        float4 x = *(const float4*)(Qg + r * HDIM + d0);
        Qs[(d0 + 0) * PADS + r] = x.x * 0.125f;
        Qs[(d0 + 1) * PADS + r] = x.y * 0.125f;
        Qs[(d0 + 2) * PADS + r] = x.z * 0.125f;
        Qs[(d0 + 3) * PADS + r] = x.w * 0.125f;
    }

    float m_i[4], l_i[4], o[4][4];
#pragma unroll
    for (int i = 0; i < 4; i++) {
        m_i[i] = -3.0e38f;
        l_i[i] = 0.0f;
#pragma unroll
        for (int j = 0; j < 4; j++) o[i][j] = 0.0f;
    }

    for (int kb = 0; kb < SEQ / 64; kb++) {
        // ---- stage K (transposed: [d][key]) ----
        const float* Kgb = Kg + (size_t)kb * 64 * HDIM;
#pragma unroll
        for (int t = 0; t < 4; t++) {
            int v = tid + t * 256;
            int r  = v >> 4;
            int d0 = (v & 15) << 2;
            float4 x = *(const float4*)(Kgb + r * HDIM + d0);
            KVs[(d0 + 0) * PADS + r] = x.x;
            KVs[(d0 + 1) * PADS + r] = x.y;
            KVs[(d0 + 2) * PADS + r] = x.z;
            KVs[(d0 + 3) * PADS + r] = x.w;
        }
        __syncthreads();

        // ---- S = (Q/8) K^T, 4x4 fragment per thread ----
        float s4[4][4];
#pragma unroll
        for (int i = 0; i < 4; i++)
#pragma unroll
            for (int j = 0; j < 4; j++) s4[i][j] = 0.0f;

#pragma unroll 8
        for (int kk = 0; kk < HDIM; kk++) {
            float4 a = *(const float4*)&Qs[kk * PADS + tr * 4];
            float4 kvv = *(const float4*)&KVs[kk * PADS + tc * 4];
            float av[4] = {a.x, a.y, a.z, a.w};
            float bv[4] = {kvv.x, kvv.y, kvv.z, kvv.w};
#pragma unroll
            for (int i = 0; i < 4; i++)
#pragma unroll
                for (int j = 0; j < 4; j++)
                    s4[i][j] = fmaf(av[i], bv[j], s4[i][j]);
        }

        // ---- online softmax (row reductions across the 16 tc-lanes) ----
#pragma unroll
        for (int i = 0; i < 4; i++) {
            float rmax = fmaxf(fmaxf(s4[i][0], s4[i][1]), fmaxf(s4[i][2], s4[i][3]));
#pragma unroll
            for (int off = 8; off >= 1; off >>= 1)
                rmax = fmaxf(rmax, __shfl_xor_sync(0xffffffffu, rmax, off));
            float mnew  = fmaxf(m_i[i], rmax);
            float alpha = __expf(m_i[i] - mnew);
            m_i[i] = mnew;
            float rs = 0.0f;
#pragma unroll
            for (int j = 0; j < 4; j++) {
                float p = __expf(s4[i][j] - mnew);
                Ps[(tc * 4 + j) * PADS + (tr * 4 + i)] = p;  // [key][q]
                rs += p;
            }
#pragma unroll
            for (int off = 8; off >= 1; off >>= 1)
                rs += __shfl_xor_sync(0xffffffffu, rs, off);
            l_i[i] = l_i[i] * alpha + rs;
#pragma unroll
            for (int j = 0; j < 4; j++) o[i][j] *= alpha;
        }
        __syncthreads();   // Ps written; K-buffer free

        // ---- stage V (natural: [seq][d]) into the K buffer ----
        const float* Vgb = Vg + (size_t)kb * 64 * HDIM;
#pragma unroll
        for (int t = 0; t < 4; t++) {
            int v = tid + t * 256;
            int r  = v >> 4;
            int d0 = (v & 15) << 2;
            *(float4*)&KVs[r * PADS + d0] = *(const float4*)(Vgb + r * HDIM + d0);
        }
        __syncthreads();

        // ---- O += P V ----
#pragma unroll 8
        for (int kk = 0; kk < 64; kk++) {
            float4 a  = *(const float4*)&Ps[kk * PADS + tr * 4];   // P[key=kk][q..]
            float4 vv = *(const float4*)&KVs[kk * PADS + tc * 4];  // V[kk][d..]
            float av[4] = {a.x, a.y, a.z, a.w};
            float bv[4] = {vv.x, vv.y, vv.z, vv.w};
#pragma unroll
            for (int i = 0; i < 4; i++)
#pragma unroll
                for (int j = 0; j < 4; j++)
                    o[i][j] = fmaf(av[i], bv[j], o[i][j]);
        }
        __syncthreads();   // done with Ps / V buffer for this block
    }

    // ---- epilogue: normalize and write [b, s, h*64+d] ----
    float* ob = g_att + ((size_t)b * SEQ + (size_t)qb * 64) * HIDDEN + h * HDIM;
#pragma unroll
    for (int i = 0; i < 4; i++) {
        float inv = 1.0f / l_i[i];
#pragma unroll
        for (int j = 0; j < 4; j++)
            ob[(size_t)(tr * 4 + i) * HIDDEN + tc * 4 + j] = o[i][j] * inv;
    }
}

// ---------------- launch ---------------------------------------------------
extern "C" void kernel_launch(void* const* d_in, const int* in_sizes, int n_in,
                              void* d_out, int out_size)
{
    const float* x     = (const float*)d_in[0];
    const float* qkv_w = (const float*)d_in[1];
    const float* qkv_b = (const float*)d_in[2];
    const float* o_w   = (const float*)d_in[3];
    const float* o_b   = (const float*)d_in[4];
    float* out = (float*)d_out;

    cudaFuncSetAttribute(attn_kernel,
                         cudaFuncAttributeMaxDynamicSharedMemorySize, ATTN_SMEM);

    dim3 blk(256);
    // 1) QKV projection + scatter
    sgemm_kernel<1><<<dim3(3 * HIDDEN / 128, MROWS / 128), blk>>>(
        x, qkv_w, qkv_b, nullptr, 3 * HIDDEN, HIDDEN);
    // 2) attention
    attn_kernel<<<dim3(SEQ / 64, HEADS, BATCH), blk, ATTN_SMEM>>>();
    // 3) output projection
    sgemm_kernel<2><<<dim3(HIDDEN / 128, MROWS / 128), blk>>>(
        nullptr, o_w, o_b, out, HIDDEN, HIDDEN);
}

// round 7
// speedup vs baseline: 2.0148x; 2.0148x over previous
#include <cuda_runtime.h>
#include <cstdint>

#define HIDDEN 1024
#define HEADS 16
#define HDIM 64
#define BATCH 2
#define SEQ 2048
#define MROWS (BATCH * SEQ)   // 4096

// ---------------- scratch (device globals; allocation-free) ----------------
__device__ float g_Q[(size_t)BATCH * HEADS * SEQ * HDIM];
__device__ float g_K[(size_t)BATCH * HEADS * SEQ * HDIM];
__device__ float g_V[(size_t)BATCH * HEADS * SEQ * HDIM];
__device__ float g_att[(size_t)BATCH * SEQ * HIDDEN];

// ---------------- helpers ---------------------------------------------------
__device__ __forceinline__ float tf32_rna(float x) {
    uint32_t u;
    asm("cvt.rna.tf32.f32 %0, %1;" : "=r"(u) : "f"(x));
    return __uint_as_float(u);
}

// D += A(16x8 tf32) * B(8x8 tf32), fp32 accumulate
__device__ __forceinline__ void mma8(float* d, const uint32_t* a, const uint32_t* b) {
    asm volatile(
        "mma.sync.aligned.m16n8k8.row.col.f32.tf32.tf32.f32 "
        "{%0,%1,%2,%3}, {%4,%5,%6,%7}, {%8,%9}, {%0,%1,%2,%3};\n"
        : "+f"(d[0]), "+f"(d[1]), "+f"(d[2]), "+f"(d[3])
        : "r"(a[0]), "r"(a[1]), "r"(a[2]), "r"(a[3]), "r"(b[0]), "r"(b[1]));
}

// ---------------- 3xTF32 GEMM:  C[m,n] = sum_k A[m,k]*B[n,k] + bias[n] ------
// MODE 1: A = x, epilogue scatters into g_Q/g_K/g_V ([b,h,s,d] layout)
// MODE 2: A = g_att (internal), epilogue writes plain row-major C
// CTA tile 128x128, BK=32, 8 warps (4m x 2n), warp tile 32x64.
// smem: Ah/Al/Bh/Bl each [128][36] fp32 (hi = tf32-rounded, lo = residual).
#define GPAD 36
#define GEMM_SMEM (4 * 128 * GPAD * (int)sizeof(float))

template <int MODE>
__global__ __launch_bounds__(256, 1) void gemm_tf32(
    const float* __restrict__ A, const float* __restrict__ B,
    const float* __restrict__ bias, float* __restrict__ C,
    int N, int K)
{
    extern __shared__ float sm[];
    float* sAh = sm;
    float* sAl = sm + 128 * GPAD;
    float* sBh = sm + 2 * 128 * GPAD;
    float* sBl = sm + 3 * 128 * GPAD;
    const uint32_t* uAh = (const uint32_t*)sAh;
    const uint32_t* uAl = (const uint32_t*)sAl;
    const uint32_t* uBh = (const uint32_t*)sBh;
    const uint32_t* uBl = (const uint32_t*)sBl;

    const int tid  = threadIdx.x;
    const int lane = tid & 31, warp = tid >> 5;
    const int g = lane >> 2, tig = lane & 3;
    const int wm = (warp >> 1) * 32;    // warp row base
    const int wn = (warp & 1) * 64;     // warp col base

    const float* Ab = (MODE == 2 ? g_att : A) + (size_t)blockIdx.y * 128 * K;
    const float* Bb = B + (size_t)blockIdx.x * 128 * K;

    const int r0 = tid >> 3;            // 0..31
    const int c0 = (tid & 7) << 2;      // 0,4,..28

    float acc[2][8][4];
#pragma unroll
    for (int mt = 0; mt < 2; mt++)
#pragma unroll
        for (int nt = 0; nt < 8; nt++)
#pragma unroll
            for (int j = 0; j < 4; j++) acc[mt][nt][j] = 0.0f;

    float4 ra[4], rb[4];
#pragma unroll
    for (int i = 0; i < 4; i++) {
        ra[i] = *(const float4*)(Ab + (size_t)(r0 + i * 32) * K + c0);
        rb[i] = *(const float4*)(Bb + (size_t)(r0 + i * 32) * K + c0);
    }

    const int NT = K / 32;
    for (int it = 0; it < NT; it++) {
        __syncthreads();   // all warps finished reading previous tile
#pragma unroll
        for (int i = 0; i < 4; i++) {
            int row = r0 + i * 32;
            float4 v = ra[i];
            float4 h = make_float4(tf32_rna(v.x), tf32_rna(v.y), tf32_rna(v.z), tf32_rna(v.w));
            float4 l = make_float4(v.x - h.x, v.y - h.y, v.z - h.z, v.w - h.w);
            *(float4*)(sAh + row * GPAD + c0) = h;
            *(float4*)(sAl + row * GPAD + c0) = l;
            v = rb[i];
            h = make_float4(tf32_rna(v.x), tf32_rna(v.y), tf32_rna(v.z), tf32_rna(v.w));
            l = make_float4(v.x - h.x, v.y - h.y, v.z - h.z, v.w - h.w);
            *(float4*)(sBh + row * GPAD + c0) = h;
            *(float4*)(sBl + row * GPAD + c0) = l;
        }
        __syncthreads();   // tile complete

        if (it + 1 < NT) {   // prefetch next tile (latency hides under MMA)
            int k0 = (it + 1) * 32;
#pragma unroll
            for (int i = 0; i < 4; i++) {
                ra[i] = *(const float4*)(Ab + (size_t)(r0 + i * 32) * K + k0 + c0);
                rb[i] = *(const float4*)(Bb + (size_t)(r0 + i * 32) * K + k0 + c0);
            }
        }

#pragma unroll
        for (int ks = 0; ks < 4; ks++) {
            const int k0 = ks * 8;
            uint32_t ah[2][4], al[2][4];
#pragma unroll
            for (int mt = 0; mt < 2; mt++) {
                int base = (wm + mt * 16 + g) * GPAD + k0 + tig;
                ah[mt][0] = uAh[base];
                ah[mt][1] = uAh[base + 8 * GPAD];
                ah[mt][2] = uAh[base + 4];
                ah[mt][3] = uAh[base + 8 * GPAD + 4];
                al[mt][0] = uAl[base];
                al[mt][1] = uAl[base + 8 * GPAD];
                al[mt][2] = uAl[base + 4];
                al[mt][3] = uAl[base + 8 * GPAD + 4];
            }
#pragma unroll
            for (int nt = 0; nt < 8; nt++) {
                int base = (wn + nt * 8 + g) * GPAD + k0 + tig;
                uint32_t bh[2] = {uBh[base], uBh[base + 4]};
                uint32_t bl[2] = {uBl[base], uBl[base + 4]};
#pragma unroll
                for (int mt = 0; mt < 2; mt++) {
                    mma8(acc[mt][nt], ah[mt], bh);   // hi*hi
                    mma8(acc[mt][nt], al[mt], bh);   // lo*hi
                    mma8(acc[mt][nt], ah[mt], bl);   // hi*lo
                }
            }
        }
    }

    // epilogue
#pragma unroll
    for (int mt = 0; mt < 2; mt++) {
#pragma unroll
        for (int half = 0; half < 2; half++) {
            int m = blockIdx.y * 128 + wm + mt * 16 + g + half * 8;
#pragma unroll
            for (int nt = 0; nt < 8; nt++) {
                int n = blockIdx.x * 128 + wn + nt * 8 + 2 * tig;
                float v0 = acc[mt][nt][half * 2 + 0] + bias[n];
                float v1 = acc[mt][nt][half * 2 + 1] + bias[n + 1];
                if (MODE == 1) {
                    int b = m >> 11;            // SEQ = 2048
                    int s = m & (SEQ - 1);
                    int h = n / 192;
                    int jj = n - h * 192;
                    float* dst = (jj < 64) ? g_Q : (jj < 128 ? g_K : g_V);
                    size_t idx = ((((size_t)b * HEADS + h) * SEQ + s) << 6) + (jj & 63);
                    *(float2*)(dst + idx) = make_float2(v0, v1);
                } else {
                    *(float2*)(C + (size_t)m * N + n) = make_float2(v0, v1);
                }
            }
        }
    }
}

// ---------------- flash attention, TF32 mma (online softmax) ----------------
// One CTA per (b, h, 128-row query block). 256 thr = 8 warps; warp owns 16
// query rows. Key blocks of 64. All fragments loaded direct from smem with
// conflict-free bank patterns (stride 68 => 4g+tig / 4tig+g cover 32 banks).
#define APAD 68
#define ATTN_SMEM ((128 + 64 + 64 + 128) * APAD * (int)sizeof(float))  // 104448

__global__ __launch_bounds__(256, 1) void attn_tf32()
{
    extern __shared__ float sm[];
    float* Qs = sm;                       // [128][APAD]  (tf32, pre-scaled)
    float* Ks = sm + 128 * APAD;          // [64][APAD]   key-major
    float* Vs = Ks + 64 * APAD;           // [64][APAD]   key-major
    float* Ps = Vs + 64 * APAD;           // [128][APAD]  row-major P
    const uint32_t* uQ = (const uint32_t*)Qs;
    const uint32_t* uK = (const uint32_t*)Ks;
    const uint32_t* uV = (const uint32_t*)Vs;
    const uint32_t* uP = (const uint32_t*)Ps;

    const int tid  = threadIdx.x;
    const int lane = tid & 31, warp = tid >> 5;
    const int g = lane >> 2, tig = lane & 3;
    const int wq = warp * 16;             // warp's query-row base

    const int qb = blockIdx.x, h = blockIdx.y, b = blockIdx.z;
    const size_t headBase = ((size_t)b * HEADS + h) * SEQ * HDIM;
    const float* Qg = g_Q + headBase + (size_t)qb * 128 * HDIM;
    const float* Kg = g_K + headBase;
    const float* Vg = g_V + headBase;

    // stage Q once: scale by 1/sqrt(64)=0.125, round to tf32
    {
        int r = tid >> 4, c = (tid & 15) << 2;
#pragma unroll
        for (int i = 0; i < 8; i++) {
            int row = r + i * 16;
            float4 v = *(const float4*)(Qg + (size_t)row * HDIM + c);
            *(float4*)(Qs + row * APAD + c) =
                make_float4(tf32_rna(v.x * 0.125f), tf32_rna(v.y * 0.125f),
                            tf32_rna(v.z * 0.125f), tf32_rna(v.w * 0.125f));
        }
    }

    float m_i[2] = {-3.0e38f, -3.0e38f};
    float l_i[2] = {0.0f, 0.0f};
    float o[8][4];
#pragma unroll
    for (int nt = 0; nt < 8; nt++)
#pragma unroll
        for (int j = 0; j < 4; j++) o[nt][j] = 0.0f;

    const int kr = tid >> 4, kc = (tid & 15) << 2;
    float4 rk[4], rv[4];
#pragma unroll
    for (int i = 0; i < 4; i++) {
        rk[i] = *(const float4*)(Kg + (size_t)(kr + i * 16) * HDIM + kc);
        rv[i] = *(const float4*)(Vg + (size_t)(kr + i * 16) * HDIM + kc);
    }

    for (int kb = 0; kb < SEQ / 64; kb++) {
        __syncthreads();   // previous PV done reading Ks/Vs (+ orders Ps rewrite)
#pragma unroll
        for (int i = 0; i < 4; i++) {
            int row = kr + i * 16;
            float4 v = rk[i];
            *(float4*)(Ks + row * APAD + kc) =
                make_float4(tf32_rna(v.x), tf32_rna(v.y), tf32_rna(v.z), tf32_rna(v.w));
            v = rv[i];
            *(float4*)(Vs + row * APAD + kc) =
                make_float4(tf32_rna(v.x), tf32_rna(v.y), tf32_rna(v.z), tf32_rna(v.w));
        }
        __syncthreads();   // K/V staged

        if (kb + 1 < SEQ / 64) {
            const float* Kn = Kg + (size_t)(kb + 1) * 64 * HDIM;
            const float* Vn = Vg + (size_t)(kb + 1) * 64 * HDIM;
#pragma unroll
            for (int i = 0; i < 4; i++) {
                rk[i] = *(const float4*)(Kn + (size_t)(kr + i * 16) * HDIM + kc);
                rv[i] = *(const float4*)(Vn + (size_t)(kr + i * 16) * HDIM + kc);
            }
        }

        // ---- S = Q K^T (16 rows x 64 keys per warp) ----
        float s[8][4];
#pragma unroll
        for (int nt = 0; nt < 8; nt++)
#pragma unroll
            for (int j = 0; j < 4; j++) s[nt][j] = 0.0f;

#pragma unroll
        for (int ks = 0; ks < 8; ks++) {
            const int k0 = ks * 8;
            uint32_t qa[4];
            int base = (wq + g) * APAD + k0 + tig;
            qa[0] = uQ[base];
            qa[1] = uQ[base + 8 * APAD];
            qa[2] = uQ[base + 4];
            qa[3] = uQ[base + 8 * APAD + 4];
#pragma unroll
            for (int nt = 0; nt < 8; nt++) {
                int bb = (nt * 8 + g) * APAD + k0 + tig;
                uint32_t kf[2] = {uK[bb], uK[bb + 4]};
                mma8(s[nt], qa, kf);
            }
        }

        // ---- online softmax (rows wq+g and wq+g+8) ----
#pragma unroll
        for (int half = 0; half < 2; half++) {
            float rmax = -3.0e38f;
#pragma unroll
            for (int nt = 0; nt < 8; nt++)
                rmax = fmaxf(rmax, fmaxf(s[nt][half * 2], s[nt][half * 2 + 1]));
            rmax = fmaxf(rmax, __shfl_xor_sync(0xffffffffu, rmax, 1));
            rmax = fmaxf(rmax, __shfl_xor_sync(0xffffffffu, rmax, 2));
            float mnew  = fmaxf(m_i[half], rmax);
            float alpha = __expf(m_i[half] - mnew);
            m_i[half] = mnew;
            float rs = 0.0f;
            int prow = (wq + g + half * 8) * APAD + 2 * tig;
#pragma unroll
            for (int nt = 0; nt < 8; nt++) {
                float p0 = __expf(s[nt][half * 2] - mnew);
                float p1 = __expf(s[nt][half * 2 + 1] - mnew);
                rs += p0 + p1;
                *(float2*)(Ps + prow + nt * 8) = make_float2(tf32_rna(p0), tf32_rna(p1));
                o[nt][half * 2]     *= alpha;
                o[nt][half * 2 + 1] *= alpha;
            }
            rs += __shfl_xor_sync(0xffffffffu, rs, 1);
            rs += __shfl_xor_sync(0xffffffffu, rs, 2);
            l_i[half] = l_i[half] * alpha + rs;
        }
        __syncwarp();   // Ps rows are warp-private; make stores visible

        // ---- O += P V ----
#pragma unroll
        for (int ks = 0; ks < 8; ks++) {
            const int k0 = ks * 8;
            uint32_t pa[4];
            int base = (wq + g) * APAD + k0 + tig;
            pa[0] = uP[base];
            pa[1] = uP[base + 8 * APAD];
            pa[2] = uP[base + 4];
            pa[3] = uP[base + 8 * APAD + 4];
#pragma unroll
            for (int nt = 0; nt < 8; nt++) {
                uint32_t vf[2] = {uV[(k0 + tig) * APAD + nt * 8 + g],
                                  uV[(k0 + tig + 4) * APAD + nt * 8 + g]};
                mma8(o[nt], pa, vf);
            }
        }
    }

    // ---- epilogue: normalize, write [b, s, h*64+d] ----
    float* ob = g_att + ((size_t)b * SEQ + (size_t)qb * 128) * HIDDEN + h * HDIM;
#pragma unroll
    for (int half = 0; half < 2; half++) {
        float inv = 1.0f / l_i[half];
        int row = wq + g + half * 8;
#pragma unroll
        for (int nt = 0; nt < 8; nt++)
            *(float2*)(ob + (size_t)row * HIDDEN + nt * 8 + 2 * tig) =
                make_float2(o[nt][half * 2] * inv, o[nt][half * 2 + 1] * inv);
    }
}

// ---------------- launch ---------------------------------------------------
extern "C" void kernel_launch(void* const* d_in, const int* in_sizes, int n_in,
                              void* d_out, int out_size)
{
    const float* x     = (const float*)d_in[0];
    const float* qkv_w = (const float*)d_in[1];
    const float* qkv_b = (const float*)d_in[2];
    const float* o_w   = (const float*)d_in[3];
    const float* o_b   = (const float*)d_in[4];
    float* out = (float*)d_out;

    cudaFuncSetAttribute(gemm_tf32<1>, cudaFuncAttributeMaxDynamicSharedMemorySize, GEMM_SMEM);
    cudaFuncSetAttribute(gemm_tf32<2>, cudaFuncAttributeMaxDynamicSharedMemorySize, GEMM_SMEM);
    cudaFuncSetAttribute(attn_tf32,   cudaFuncAttributeMaxDynamicSharedMemorySize, ATTN_SMEM);

    dim3 blk(256);
    // 1) QKV projection (3xTF32) + scatter to [b,h,s,d]
    gemm_tf32<1><<<dim3(3 * HIDDEN / 128, MROWS / 128), blk, GEMM_SMEM>>>(
        x, qkv_w, qkv_b, nullptr, 3 * HIDDEN, HIDDEN);
    // 2) attention (1xTF32)
    attn_tf32<<<dim3(SEQ / 128, HEADS, BATCH), blk, ATTN_SMEM>>>();
    // 3) output projection (3xTF32)
    gemm_tf32<2><<<dim3(HIDDEN / 128, MROWS / 128), blk, GEMM_SMEM>>>(
        nullptr, o_w, o_b, out, HIDDEN, HIDDEN);
}

// round 9
// speedup vs baseline: 2.8343x; 1.4068x over previous
#include <cuda_runtime.h>
#include <cstdint>

#define HIDDEN 1024
#define HEADS 16
#define HDIM 64
#define BATCH 2
#define SEQ 2048
#define MROWS (BATCH * SEQ)   // 4096

// ---------------- scratch (device globals; allocation-free) ----------------
__device__ float g_Q[(size_t)BATCH * HEADS * SEQ * HDIM];
__device__ float g_K[(size_t)BATCH * HEADS * SEQ * HDIM];
__device__ float g_V[(size_t)BATCH * HEADS * SEQ * HDIM];
__device__ float g_att[(size_t)BATCH * SEQ * HIDDEN];

// ---------------- helpers ---------------------------------------------------
__device__ __forceinline__ float tf32_rna(float x) {
    uint32_t u;
    asm("cvt.rna.tf32.f32 %0, %1;" : "=r"(u) : "f"(x));
    return __uint_as_float(u);
}

// D += A(16x8 tf32) * B(8x8 tf32), fp32 accumulate
__device__ __forceinline__ void mma8(float* d, const uint32_t* a, const uint32_t* b) {
    asm volatile(
        "mma.sync.aligned.m16n8k8.row.col.f32.tf32.tf32.f32 "
        "{%0,%1,%2,%3}, {%4,%5,%6,%7}, {%8,%9}, {%0,%1,%2,%3};\n"
        : "+f"(d[0]), "+f"(d[1]), "+f"(d[2]), "+f"(d[3])
        : "r"(a[0]), "r"(a[1]), "r"(a[2]), "r"(a[3]), "r"(b[0]), "r"(b[1]));
}

// ---------------- 1xTF32 GEMM:  C[m,n] = sum_k A[m,k]*B[n,k] + bias[n] ------
// MODE 1: A = x, epilogue scatters into g_Q/g_K/g_V ([b,h,s,d] layout)
// MODE 2: A = g_att (internal), epilogue writes plain row-major C
// CTA tile 128x128, BK=32, 8 warps (4m x 2n), warp tile 32x64.
// Double-buffered smem: 2 x (A[128][36] + B[128][36]) tf32.
#define GPAD 36
#define GBUF (2 * 128 * GPAD)                       // floats per buffer (A+B)
#define GEMM_SMEM (2 * GBUF * (int)sizeof(float))   // 73728 bytes

template <int MODE>
__global__ __launch_bounds__(256, 1) void gemm_tf32(
    const float* __restrict__ A, const float* __restrict__ B,
    const float* __restrict__ bias, float* __restrict__ C,
    int N, int K)
{
    extern __shared__ float sm[];

    const int tid  = threadIdx.x;
    const int lane = tid & 31, warp = tid >> 5;
    const int g = lane >> 2, tig = lane & 3;
    const int wm = (warp >> 1) * 32;    // warp row base
    const int wn = (warp & 1) * 64;     // warp col base

    const float* Ab = (MODE == 2 ? g_att : A) + (size_t)blockIdx.y * 128 * K;
    const float* Bb = B + (size_t)blockIdx.x * 128 * K;

    const int r0 = tid >> 3;            // 0..31
    const int c0 = (tid & 7) << 2;      // 0,4,..28

    float acc[2][8][4];
#pragma unroll
    for (int mt = 0; mt < 2; mt++)
#pragma unroll
        for (int nt = 0; nt < 8; nt++)
#pragma unroll
            for (int j = 0; j < 4; j++) acc[mt][nt][j] = 0.0f;

    float4 ra[4], rb[4];
#pragma unroll
    for (int i = 0; i < 4; i++) {
        ra[i] = *(const float4*)(Ab + (size_t)(r0 + i * 32) * K + c0);
        rb[i] = *(const float4*)(Bb + (size_t)(r0 + i * 32) * K + c0);
    }
    // stage buffer 0
    {
        float* sA = sm;
        float* sB = sm + 128 * GPAD;
#pragma unroll
        for (int i = 0; i < 4; i++) {
            int row = r0 + i * 32;
            float4 v = ra[i];
            *(float4*)(sA + row * GPAD + c0) =
                make_float4(tf32_rna(v.x), tf32_rna(v.y), tf32_rna(v.z), tf32_rna(v.w));
            v = rb[i];
            *(float4*)(sB + row * GPAD + c0) =
                make_float4(tf32_rna(v.x), tf32_rna(v.y), tf32_rna(v.z), tf32_rna(v.w));
        }
    }

    const int NT = K / 32;
    for (int it = 0; it < NT; it++) {
        __syncthreads();   // buf[it&1] staged; prior reads of buf[(it+1)&1] done
        const uint32_t* uA = (const uint32_t*)(sm + (it & 1) * GBUF);
        const uint32_t* uB = uA + 128 * GPAD;

        if (it + 1 < NT) {   // prefetch next tile to registers
            int k0 = (it + 1) * 32;
#pragma unroll
            for (int i = 0; i < 4; i++) {
                ra[i] = *(const float4*)(Ab + (size_t)(r0 + i * 32) * K + k0 + c0);
                rb[i] = *(const float4*)(Bb + (size_t)(r0 + i * 32) * K + k0 + c0);
            }
        }

#pragma unroll
        for (int ks = 0; ks < 4; ks++) {
            const int k0 = ks * 8;
            uint32_t ah[2][4];
#pragma unroll
            for (int mt = 0; mt < 2; mt++) {
                int base = (wm + mt * 16 + g) * GPAD + k0 + tig;
                ah[mt][0] = uA[base];
                ah[mt][1] = uA[base + 8 * GPAD];
                ah[mt][2] = uA[base + 4];
                ah[mt][3] = uA[base + 8 * GPAD + 4];
            }
#pragma unroll
            for (int nt = 0; nt < 8; nt++) {
                int base = (wn + nt * 8 + g) * GPAD + k0 + tig;
                uint32_t bh[2] = {uB[base], uB[base + 4]};
                mma8(acc[0][nt], ah[0], bh);
                mma8(acc[1][nt], ah[1], bh);
            }
        }

        if (it + 1 < NT) {   // stage into the other buffer (safe post-sync)
            float* sA = sm + ((it + 1) & 1) * GBUF;
            float* sB = sA + 128 * GPAD;
#pragma unroll
            for (int i = 0; i < 4; i++) {
                int row = r0 + i * 32;
                float4 v = ra[i];
                *(float4*)(sA + row * GPAD + c0) =
                    make_float4(tf32_rna(v.x), tf32_rna(v.y), tf32_rna(v.z), tf32_rna(v.w));
                v = rb[i];
                *(float4*)(sB + row * GPAD + c0) =
                    make_float4(tf32_rna(v.x), tf32_rna(v.y), tf32_rna(v.z), tf32_rna(v.w));
            }
        }
    }

    // epilogue
#pragma unroll
    for (int mt = 0; mt < 2; mt++) {
#pragma unroll
        for (int half = 0; half < 2; half++) {
            int m = blockIdx.y * 128 + wm + mt * 16 + g + half * 8;
#pragma unroll
            for (int nt = 0; nt < 8; nt++) {
                int n = blockIdx.x * 128 + wn + nt * 8 + 2 * tig;
                float v0 = acc[mt][nt][half * 2 + 0] + bias[n];
                float v1 = acc[mt][nt][half * 2 + 1] + bias[n + 1];
                if (MODE == 1) {
                    int b = m >> 11;            // SEQ = 2048
                    int s = m & (SEQ - 1);
                    int h = n / 192;
                    int jj = n - h * 192;
                    float* dst = (jj < 64) ? g_Q : (jj < 128 ? g_K : g_V);
                    size_t idx = ((((size_t)b * HEADS + h) * SEQ + s) << 6) + (jj & 63);
                    *(float2*)(dst + idx) = make_float2(v0, v1);
                } else {
                    *(float2*)(C + (size_t)m * N + n) = make_float2(v0, v1);
                }
            }
        }
    }
}

// ---------------- flash attention, TF32 mma (online softmax) ----------------
// One CTA per (b, h, 128-row query block). 256 thr = 8 warps; warp owns 16
// query rows. Key blocks of 64, double-buffered K/V (one syncthreads/block).
#define APAD 68
#define AKV (64 * APAD)
#define ATTN_SMEM ((128 + 2 * 64 + 2 * 64 + 128) * APAD * (int)sizeof(float)) // 139264

__global__ __launch_bounds__(256, 1) void attn_tf32()
{
    extern __shared__ float sm[];
    float* Qs = sm;                         // [128][APAD]  (tf32, pre-scaled)
    float* Ks = sm + 128 * APAD;            // 2 x [64][APAD] key-major
    float* Vs = Ks + 2 * AKV;               // 2 x [64][APAD] key-major
    float* Ps = Vs + 2 * AKV;               // [128][APAD]  row-major P
    const uint32_t* uQ = (const uint32_t*)Qs;
    const uint32_t* uP = (const uint32_t*)Ps;

    const int tid  = threadIdx.x;
    const int lane = tid & 31, warp = tid >> 5;
    const int g = lane >> 2, tig = lane & 3;
    const int wq = warp * 16;               // warp's query-row base

    const int qb = blockIdx.x, h = blockIdx.y, b = blockIdx.z;
    const size_t headBase = ((size_t)b * HEADS + h) * SEQ * HDIM;
    const float* Qg = g_Q + headBase + (size_t)qb * 128 * HDIM;
    const float* Kg = g_K + headBase;
    const float* Vg = g_V + headBase;

    // stage Q once: scale by 1/sqrt(64)=0.125, round to tf32
    {
        int r = tid >> 4, c = (tid & 15) << 2;
#pragma unroll
        for (int i = 0; i < 8; i++) {
            int row = r + i * 16;
            float4 v = *(const float4*)(Qg + (size_t)row * HDIM + c);
            *(float4*)(Qs + row * APAD + c) =
                make_float4(tf32_rna(v.x * 0.125f), tf32_rna(v.y * 0.125f),
                            tf32_rna(v.z * 0.125f), tf32_rna(v.w * 0.125f));
        }
    }

    float m_i[2] = {-3.0e38f, -3.0e38f};
    float l_i[2] = {0.0f, 0.0f};
    float o[8][4];
#pragma unroll
    for (int nt = 0; nt < 8; nt++)
#pragma unroll
        for (int j = 0; j < 4; j++) o[nt][j] = 0.0f;

    const int kr = tid >> 4, kc = (tid & 15) << 2;
    float4 rk[4], rv[4];
#pragma unroll
    for (int i = 0; i < 4; i++) {
        rk[i] = *(const float4*)(Kg + (size_t)(kr + i * 16) * HDIM + kc);
        rv[i] = *(const float4*)(Vg + (size_t)(kr + i * 16) * HDIM + kc);
    }
    // stage K/V buffer 0
#pragma unroll
    for (int i = 0; i < 4; i++) {
        int row = kr + i * 16;
        float4 v = rk[i];
        *(float4*)(Ks + row * APAD + kc) =
            make_float4(tf32_rna(v.x), tf32_rna(v.y), tf32_rna(v.z), tf32_rna(v.w));
        v = rv[i];
        *(float4*)(Vs + row * APAD + kc) =
            make_float4(tf32_rna(v.x), tf32_rna(v.y), tf32_rna(v.z), tf32_rna(v.w));
    }

    const int NB = SEQ / 64;
    for (int kb = 0; kb < NB; kb++) {
        __syncthreads();   // buf[kb&1] staged; reads of buf[(kb+1)&1] (iter kb-1) done
        const uint32_t* uK = (const uint32_t*)(Ks + (kb & 1) * AKV);
        const uint32_t* uV = (const uint32_t*)(Vs + (kb & 1) * AKV);

        if (kb + 1 < NB) {   // prefetch next K/V block to registers
            const float* Kn = Kg + (size_t)(kb + 1) * 64 * HDIM;
            const float* Vn = Vg + (size_t)(kb + 1) * 64 * HDIM;
#pragma unroll
            for (int i = 0; i < 4; i++) {
                rk[i] = *(const float4*)(Kn + (size_t)(kr + i * 16) * HDIM + kc);
                rv[i] = *(const float4*)(Vn + (size_t)(kr + i * 16) * HDIM + kc);
            }
        }

        // ---- S = Q K^T (16 rows x 64 keys per warp) ----
        float s[8][4];
#pragma unroll
        for (int nt = 0; nt < 8; nt++)
#pragma unroll
            for (int j = 0; j < 4; j++) s[nt][j] = 0.0f;

#pragma unroll
        for (int ks = 0; ks < 8; ks++) {
            const int k0 = ks * 8;
            uint32_t qa[4];
            int base = (wq + g) * APAD + k0 + tig;
            qa[0] = uQ[base];
            qa[1] = uQ[base + 8 * APAD];
            qa[2] = uQ[base + 4];
            qa[3] = uQ[base + 8 * APAD + 4];
#pragma unroll
            for (int nt = 0; nt < 8; nt++) {
                int bb = (nt * 8 + g) * APAD + k0 + tig;
                uint32_t kf[2] = {uK[bb], uK[bb + 4]};
                mma8(s[nt], qa, kf);
            }
        }

        // ---- online softmax (rows wq+g and wq+g+8) ----
#pragma unroll
        for (int half = 0; half < 2; half++) {
            float rmax = -3.0e38f;
#pragma unroll
            for (int nt = 0; nt < 8; nt++)
                rmax = fmaxf(rmax, fmaxf(s[nt][half * 2], s[nt][half * 2 + 1]));
            rmax = fmaxf(rmax, __shfl_xor_sync(0xffffffffu, rmax, 1));
            rmax = fmaxf(rmax, __shfl_xor_sync(0xffffffffu, rmax, 2));
            float mnew  = fmaxf(m_i[half], rmax);
            float alpha = __expf(m_i[half] - mnew);
            m_i[half] = mnew;
            float rs = 0.0f;
            int prow = (wq + g + half * 8) * APAD + 2 * tig;
#pragma unroll
            for (int nt = 0; nt < 8; nt++) {
                float p0 = __expf(s[nt][half * 2] - mnew);
                float p1 = __expf(s[nt][half * 2 + 1] - mnew);
                rs += p0 + p1;
                *(float2*)(Ps + prow + nt * 8) = make_float2(tf32_rna(p0), tf32_rna(p1));
                o[nt][half * 2]     *= alpha;
                o[nt][half * 2 + 1] *= alpha;
            }
            rs += __shfl_xor_sync(0xffffffffu, rs, 1);
            rs += __shfl_xor_sync(0xffffffffu, rs, 2);
            l_i[half] = l_i[half] * alpha + rs;
        }
        __syncwarp();   // Ps rows are warp-private; make stores visible

        if (kb + 1 < NB) {   // stage next K/V into the other buffer
            float* Kd = Ks + ((kb + 1) & 1) * AKV;
            float* Vd = Vs + ((kb + 1) & 1) * AKV;
#pragma unroll
            for (int i = 0; i < 4; i++) {
                int row = kr + i * 16;
                float4 v = rk[i];
                *(float4*)(Kd + row * APAD + kc) =
                    make_float4(tf32_rna(v.x), tf32_rna(v.y), tf32_rna(v.z), tf32_rna(v.w));
                v = rv[i];
                *(float4*)(Vd + row * APAD + kc) =
                    make_float4(tf32_rna(v.x), tf32_rna(v.y), tf32_rna(v.z), tf32_rna(v.w));
            }
        }

        // ---- O += P V ----
#pragma unroll
        for (int ks = 0; ks < 8; ks++) {
            const int k0 = ks * 8;
            uint32_t pa[4];
            int base = (wq + g) * APAD + k0 + tig;
            pa[0] = uP[base];
            pa[1] = uP[base + 8 * APAD];
            pa[2] = uP[base + 4];
            pa[3] = uP[base + 8 * APAD + 4];
#pragma unroll
            for (int nt = 0; nt < 8; nt++) {
                uint32_t vf[2] = {uV[(k0 + tig) * APAD + nt * 8 + g],
                                  uV[(k0 + tig + 4) * APAD + nt * 8 + g]};
                mma8(o[nt], pa, vf);
            }
        }
    }

    // ---- epilogue: normalize, write [b, s, h*64+d] ----
    float* ob = g_att + ((size_t)b * SEQ + (size_t)qb * 128) * HIDDEN + h * HDIM;
#pragma unroll
    for (int half = 0; half < 2; half++) {
        float inv = 1.0f / l_i[half];
        int row = wq + g + half * 8;
#pragma unroll
        for (int nt = 0; nt < 8; nt++)
            *(float2*)(ob + (size_t)row * HIDDEN + nt * 8 + 2 * tig) =
                make_float2(o[nt][half * 2] * inv, o[nt][half * 2 + 1] * inv);
    }
}

// ---------------- launch ---------------------------------------------------
extern "C" void kernel_launch(void* const* d_in, const int* in_sizes, int n_in,
                              void* d_out, int out_size)
{
    const float* x     = (const float*)d_in[0];
    const float* qkv_w = (const float*)d_in[1];
    const float* qkv_b = (const float*)d_in[2];
    const float* o_w   = (const float*)d_in[3];
    const float* o_b   = (const float*)d_in[4];
    float* out = (float*)d_out;

    cudaFuncSetAttribute(gemm_tf32<1>, cudaFuncAttributeMaxDynamicSharedMemorySize, GEMM_SMEM);
    cudaFuncSetAttribute(gemm_tf32<2>, cudaFuncAttributeMaxDynamicSharedMemorySize, GEMM_SMEM);
    cudaFuncSetAttribute(attn_tf32,   cudaFuncAttributeMaxDynamicSharedMemorySize, ATTN_SMEM);

    dim3 blk(256);
    // 1) QKV projection (1xTF32) + scatter to [b,h,s,d]
    gemm_tf32<1><<<dim3(3 * HIDDEN / 128, MROWS / 128), blk, GEMM_SMEM>>>(
        x, qkv_w, qkv_b, nullptr, 3 * HIDDEN, HIDDEN);
    // 2) attention (1xTF32, double-buffered K/V)
    attn_tf32<<<dim3(SEQ / 128, HEADS, BATCH), blk, ATTN_SMEM>>>();
    // 3) output projection (1xTF32)
    gemm_tf32<2><<<dim3(HIDDEN / 128, MROWS / 128), blk, GEMM_SMEM>>>(
        nullptr, o_w, o_b, out, HIDDEN, HIDDEN);
}

// round 10
// speedup vs baseline: 2.8964x; 1.0219x over previous
#include <cuda_runtime.h>
#include <cstdint>

#define HIDDEN 1024
#define HEADS 16
#define HDIM 64
#define BATCH 2
#define SEQ 2048
#define MROWS (BATCH * SEQ)   // 4096

// ---------------- scratch (device globals; allocation-free) ----------------
__device__ float g_Q[(size_t)BATCH * HEADS * SEQ * HDIM];
__device__ float g_K[(size_t)BATCH * HEADS * SEQ * HDIM];
__device__ float g_V[(size_t)BATCH * HEADS * SEQ * HDIM];
__device__ float g_att[(size_t)BATCH * SEQ * HIDDEN];

// ---------------- helpers ---------------------------------------------------
__device__ __forceinline__ float tf32_rna(float x) {
    uint32_t u;
    asm("cvt.rna.tf32.f32 %0, %1;" : "=r"(u) : "f"(x));
    return __uint_as_float(u);
}

// D += A(16x8 tf32) * B(8x8 tf32), fp32 accumulate
__device__ __forceinline__ void mma8(float* d, const uint32_t* a, const uint32_t* b) {
    asm volatile(
        "mma.sync.aligned.m16n8k8.row.col.f32.tf32.tf32.f32 "
        "{%0,%1,%2,%3}, {%4,%5,%6,%7}, {%8,%9}, {%0,%1,%2,%3};\n"
        : "+f"(d[0]), "+f"(d[1]), "+f"(d[2]), "+f"(d[3])
        : "r"(a[0]), "r"(a[1]), "r"(a[2]), "r"(a[3]), "r"(b[0]), "r"(b[1]));
}

// ---------------- 1xTF32 GEMM:  C[m,n] = sum_k A[m,k]*B[n,k] + bias[n] ------
// MODE 1: A = x, epilogue scatters into g_Q/g_K/g_V ([b,h,s,d] layout)
// MODE 2: A = g_att (internal), epilogue writes plain row-major C
// CTA tile 128x128, BK=32, 512 threads = 16 warps (4m x 4n), warp tile 32x32.
// Double-buffered smem: 2 x (A[128][36] + B[128][36]) tf32.
#define GPAD 36
#define GBUF (2 * 128 * GPAD)                       // floats per buffer (A+B)
#define GEMM_SMEM (2 * GBUF * (int)sizeof(float))   // 73728 bytes

template <int MODE>
__global__ __launch_bounds__(512, 1) void gemm_tf32(
    const float* __restrict__ A, const float* __restrict__ B,
    const float* __restrict__ bias, float* __restrict__ C,
    int N, int K)
{
    extern __shared__ float sm[];

    const int tid  = threadIdx.x;
    const int lane = tid & 31, warp = tid >> 5;   // 0..15
    const int g = lane >> 2, tig = lane & 3;
    const int wm = (warp >> 2) * 32;    // warp row base (0,32,64,96)
    const int wn = (warp & 3) * 32;     // warp col base (0,32,64,96)

    const float* Ab = (MODE == 2 ? g_att : A) + (size_t)blockIdx.y * 128 * K;
    const float* Bb = B + (size_t)blockIdx.x * 128 * K;

    const int r0 = tid >> 3;            // 0..63
    const int c0 = (tid & 7) << 2;      // 0,4,..28

    float acc[2][4][4];
#pragma unroll
    for (int mt = 0; mt < 2; mt++)
#pragma unroll
        for (int nt = 0; nt < 4; nt++)
#pragma unroll
            for (int j = 0; j < 4; j++) acc[mt][nt][j] = 0.0f;

    float4 ra[2], rb[2];
#pragma unroll
    for (int i = 0; i < 2; i++) {
        ra[i] = *(const float4*)(Ab + (size_t)(r0 + i * 64) * K + c0);
        rb[i] = *(const float4*)(Bb + (size_t)(r0 + i * 64) * K + c0);
    }
    // stage buffer 0
    {
        float* sA = sm;
        float* sB = sm + 128 * GPAD;
#pragma unroll
        for (int i = 0; i < 2; i++) {
            int row = r0 + i * 64;
            float4 v = ra[i];
            *(float4*)(sA + row * GPAD + c0) =
                make_float4(tf32_rna(v.x), tf32_rna(v.y), tf32_rna(v.z), tf32_rna(v.w));
            v = rb[i];
            *(float4*)(sB + row * GPAD + c0) =
                make_float4(tf32_rna(v.x), tf32_rna(v.y), tf32_rna(v.z), tf32_rna(v.w));
        }
    }

    const int NT = K / 32;
    for (int it = 0; it < NT; it++) {
        __syncthreads();   // buf[it&1] staged; prior reads of buf[(it+1)&1] done
        const uint32_t* uA = (const uint32_t*)(sm + (it & 1) * GBUF);
        const uint32_t* uB = uA + 128 * GPAD;

        if (it + 1 < NT) {   // prefetch next tile to registers
            int k0 = (it + 1) * 32;
#pragma unroll
            for (int i = 0; i < 2; i++) {
                ra[i] = *(const float4*)(Ab + (size_t)(r0 + i * 64) * K + k0 + c0);
                rb[i] = *(const float4*)(Bb + (size_t)(r0 + i * 64) * K + k0 + c0);
            }
        }

#pragma unroll
        for (int ks = 0; ks < 4; ks++) {
            const int k0 = ks * 8;
            uint32_t ah[2][4];
#pragma unroll
            for (int mt = 0; mt < 2; mt++) {
                int base = (wm + mt * 16 + g) * GPAD + k0 + tig;
                ah[mt][0] = uA[base];
                ah[mt][1] = uA[base + 8 * GPAD];
                ah[mt][2] = uA[base + 4];
                ah[mt][3] = uA[base + 8 * GPAD + 4];
            }
#pragma unroll
            for (int nt = 0; nt < 4; nt++) {
                int base = (wn + nt * 8 + g) * GPAD + k0 + tig;
                uint32_t bh[2] = {uB[base], uB[base + 4]};
                mma8(acc[0][nt], ah[0], bh);
                mma8(acc[1][nt], ah[1], bh);
            }
        }

        if (it + 1 < NT) {   // stage into the other buffer (safe post-sync)
            float* sA = sm + ((it + 1) & 1) * GBUF;
            float* sB = sA + 128 * GPAD;
#pragma unroll
            for (int i = 0; i < 2; i++) {
                int row = r0 + i * 64;
                float4 v = ra[i];
                *(float4*)(sA + row * GPAD + c0) =
                    make_float4(tf32_rna(v.x), tf32_rna(v.y), tf32_rna(v.z), tf32_rna(v.w));
                v = rb[i];
                *(float4*)(sB + row * GPAD + c0) =
                    make_float4(tf32_rna(v.x), tf32_rna(v.y), tf32_rna(v.z), tf32_rna(v.w));
            }
        }
    }

    // epilogue
#pragma unroll
    for (int mt = 0; mt < 2; mt++) {
#pragma unroll
        for (int half = 0; half < 2; half++) {
            int m = blockIdx.y * 128 + wm + mt * 16 + g + half * 8;
#pragma unroll
            for (int nt = 0; nt < 4; nt++) {
                int n = blockIdx.x * 128 + wn + nt * 8 + 2 * tig;
                float v0 = acc[mt][nt][half * 2 + 0] + bias[n];
                float v1 = acc[mt][nt][half * 2 + 1] + bias[n + 1];
                if (MODE == 1) {
                    int b = m >> 11;            // SEQ = 2048
                    int s = m & (SEQ - 1);
                    int h = n / 192;
                    int jj = n - h * 192;
                    float* dst = (jj < 64) ? g_Q : (jj < 128 ? g_K : g_V);
                    size_t idx = ((((size_t)b * HEADS + h) * SEQ + s) << 6) + (jj & 63);
                    *(float2*)(dst + idx) = make_float2(v0, v1);
                } else {
                    *(float2*)(C + (size_t)m * N + n) = make_float2(v0, v1);
                }
            }
        }
    }
}

// ---------------- flash attention, TF32 mma (online softmax) ----------------
// One CTA per (b, h, 256-row query block). 512 thr = 16 warps; warp owns 16
// query rows. Key blocks of 64, double-buffered K/V (one syncthreads/block).
// K/V staging happens between softmax and PV (short register live range).
#define APAD 68
#define AKV (64 * APAD)
#define ATTN_SMEM ((256 + 2 * 64 + 2 * 64 + 256) * APAD * (int)sizeof(float)) // 208896

__global__ __launch_bounds__(512, 1) void attn_tf32()
{
    extern __shared__ float sm[];
    float* Qs = sm;                         // [256][APAD]  (tf32, pre-scaled)
    float* Ks = sm + 256 * APAD;            // 2 x [64][APAD] key-major
    float* Vs = Ks + 2 * AKV;               // 2 x [64][APAD] key-major
    float* Ps = Vs + 2 * AKV;               // [256][APAD]  row-major P
    const uint32_t* uQ = (const uint32_t*)Qs;
    const uint32_t* uP = (const uint32_t*)Ps;

    const int tid  = threadIdx.x;
    const int lane = tid & 31, warp = tid >> 5;   // 0..15
    const int g = lane >> 2, tig = lane & 3;
    const int wq = warp * 16;               // warp's query-row base (0..240)

    const int qb = blockIdx.x, h = blockIdx.y, b = blockIdx.z;
    const size_t headBase = ((size_t)b * HEADS + h) * SEQ * HDIM;
    const float* Qg = g_Q + headBase + (size_t)qb * 256 * HDIM;
    const float* Kg = g_K + headBase;
    const float* Vg = g_V + headBase;

    // stage Q once: scale by 1/sqrt(64)=0.125, round to tf32
    {
        int r = tid >> 4, c = (tid & 15) << 2;   // r 0..31, c 0..60
#pragma unroll
        for (int i = 0; i < 8; i++) {
            int row = r + i * 32;
            float4 v = *(const float4*)(Qg + (size_t)row * HDIM + c);
            *(float4*)(Qs + row * APAD + c) =
                make_float4(tf32_rna(v.x * 0.125f), tf32_rna(v.y * 0.125f),
                            tf32_rna(v.z * 0.125f), tf32_rna(v.w * 0.125f));
        }
    }

    float m_i[2] = {-3.0e38f, -3.0e38f};
    float l_i[2] = {0.0f, 0.0f};
    float o[8][4];
#pragma unroll
    for (int nt = 0; nt < 8; nt++)
#pragma unroll
        for (int j = 0; j < 4; j++) o[nt][j] = 0.0f;

    const int kr = tid >> 4, kc = (tid & 15) << 2;   // kr 0..31
    // stage K/V buffer 0 (rows kr, kr+32)
#pragma unroll
    for (int i = 0; i < 2; i++) {
        int row = kr + i * 32;
        float4 v = *(const float4*)(Kg + (size_t)row * HDIM + kc);
        *(float4*)(Ks + row * APAD + kc) =
            make_float4(tf32_rna(v.x), tf32_rna(v.y), tf32_rna(v.z), tf32_rna(v.w));
        v = *(const float4*)(Vg + (size_t)row * HDIM + kc);
        *(float4*)(Vs + row * APAD + kc) =
            make_float4(tf32_rna(v.x), tf32_rna(v.y), tf32_rna(v.z), tf32_rna(v.w));
    }

    const int NB = SEQ / 64;
    for (int kb = 0; kb < NB; kb++) {
        __syncthreads();   // buf[kb&1] staged; reads of buf[(kb+1)&1] (iter kb-1) done
        const uint32_t* uK = (const uint32_t*)(Ks + (kb & 1) * AKV);
        const uint32_t* uV = (const uint32_t*)(Vs + (kb & 1) * AKV);

        // ---- S = Q K^T (16 rows x 64 keys per warp) ----
        float s[8][4];
#pragma unroll
        for (int nt = 0; nt < 8; nt++)
#pragma unroll
            for (int j = 0; j < 4; j++) s[nt][j] = 0.0f;

#pragma unroll
        for (int ks = 0; ks < 8; ks++) {
            const int k0 = ks * 8;
            uint32_t qa[4];
            int base = (wq + g) * APAD + k0 + tig;
            qa[0] = uQ[base];
            qa[1] = uQ[base + 8 * APAD];
            qa[2] = uQ[base + 4];
            qa[3] = uQ[base + 8 * APAD + 4];
#pragma unroll
            for (int nt = 0; nt < 8; nt++) {
                int bb = (nt * 8 + g) * APAD + k0 + tig;
                uint32_t kf[2] = {uK[bb], uK[bb + 4]};
                mma8(s[nt], qa, kf);
            }
        }

        // ---- online softmax (rows wq+g and wq+g+8) ----
#pragma unroll
        for (int half = 0; half < 2; half++) {
            float rmax = -3.0e38f;
#pragma unroll
            for (int nt = 0; nt < 8; nt++)
                rmax = fmaxf(rmax, fmaxf(s[nt][half * 2], s[nt][half * 2 + 1]));
            rmax = fmaxf(rmax, __shfl_xor_sync(0xffffffffu, rmax, 1));
            rmax = fmaxf(rmax, __shfl_xor_sync(0xffffffffu, rmax, 2));
            float mnew  = fmaxf(m_i[half], rmax);
            float alpha = __expf(m_i[half] - mnew);
            m_i[half] = mnew;
            float rs = 0.0f;
            int prow = (wq + g + half * 8) * APAD + 2 * tig;
#pragma unroll
            for (int nt = 0; nt < 8; nt++) {
                float p0 = __expf(s[nt][half * 2] - mnew);
                float p1 = __expf(s[nt][half * 2 + 1] - mnew);
                rs += p0 + p1;
                *(float2*)(Ps + prow + nt * 8) = make_float2(tf32_rna(p0), tf32_rna(p1));
                o[nt][half * 2]     *= alpha;
                o[nt][half * 2 + 1] *= alpha;
            }
            rs += __shfl_xor_sync(0xffffffffu, rs, 1);
            rs += __shfl_xor_sync(0xffffffffu, rs, 2);
            l_i[half] = l_i[half] * alpha + rs;
        }
        __syncwarp();   // Ps rows are warp-private; make stores visible

        if (kb + 1 < NB) {   // stage next K/V into the other buffer
            // (previous PV read of this buffer was fenced by the loop-top sync)
            const float* Kn = Kg + (size_t)(kb + 1) * 64 * HDIM;
            const float* Vn = Vg + (size_t)(kb + 1) * 64 * HDIM;
            float* Kd = Ks + ((kb + 1) & 1) * AKV;
            float* Vd = Vs + ((kb + 1) & 1) * AKV;
#pragma unroll
            for (int i = 0; i < 2; i++) {
                int row = kr + i * 32;
                float4 v = *(const float4*)(Kn + (size_t)row * HDIM + kc);
                *(float4*)(Kd + row * APAD + kc) =
                    make_float4(tf32_rna(v.x), tf32_rna(v.y), tf32_rna(v.z), tf32_rna(v.w));
                v = *(const float4*)(Vn + (size_t)row * HDIM + kc);
                *(float4*)(Vd + row * APAD + kc) =
                    make_float4(tf32_rna(v.x), tf32_rna(v.y), tf32_rna(v.z), tf32_rna(v.w));
            }
        }

        // ---- O += P V ----
#pragma unroll
        for (int ks = 0; ks < 8; ks++) {
            const int k0 = ks * 8;
            uint32_t pa[4];
            int base = (wq + g) * APAD + k0 + tig;
            pa[0] = uP[base];
            pa[1] = uP[base + 8 * APAD];
            pa[2] = uP[base + 4];
            pa[3] = uP[base + 8 * APAD + 4];
#pragma unroll
            for (int nt = 0; nt < 8; nt++) {
                uint32_t vf[2] = {uV[(k0 + tig) * APAD + nt * 8 + g],
                                  uV[(k0 + tig + 4) * APAD + nt * 8 + g]};
                mma8(o[nt], pa, vf);
            }
        }
    }

    // ---- epilogue: normalize, write [b, s, h*64+d] ----
    float* ob = g_att + ((size_t)b * SEQ + (size_t)qb * 256) * HIDDEN + h * HDIM;
#pragma unroll
    for (int half = 0; half < 2; half++) {
        float inv = 1.0f / l_i[half];
        int row = wq + g + half * 8;
#pragma unroll
        for (int nt = 0; nt < 8; nt++)
            *(float2*)(ob + (size_t)row * HIDDEN + nt * 8 + 2 * tig) =
                make_float2(o[nt][half * 2] * inv, o[nt][half * 2 + 1] * inv);
    }
}

// ---------------- launch ---------------------------------------------------
extern "C" void kernel_launch(void* const* d_in, const int* in_sizes, int n_in,
                              void* d_out, int out_size)
{
    const float* x     = (const float*)d_in[0];
    const float* qkv_w = (const float*)d_in[1];
    const float* qkv_b = (const float*)d_in[2];
    const float* o_w   = (const float*)d_in[3];
    const float* o_b   = (const float*)d_in[4];
    float* out = (float*)d_out;

    cudaFuncSetAttribute(gemm_tf32<1>, cudaFuncAttributeMaxDynamicSharedMemorySize, GEMM_SMEM);
    cudaFuncSetAttribute(gemm_tf32<2>, cudaFuncAttributeMaxDynamicSharedMemorySize, GEMM_SMEM);
    cudaFuncSetAttribute(attn_tf32,   cudaFuncAttributeMaxDynamicSharedMemorySize, ATTN_SMEM);

    dim3 blk(512);
    // 1) QKV projection (1xTF32) + scatter to [b,h,s,d]
    gemm_tf32<1><<<dim3(3 * HIDDEN / 128, MROWS / 128), blk, GEMM_SMEM>>>(
        x, qkv_w, qkv_b, nullptr, 3 * HIDDEN, HIDDEN);
    // 2) attention (1xTF32, 256-row query blocks, 16 warps)
    attn_tf32<<<dim3(SEQ / 256, HEADS, BATCH), blk, ATTN_SMEM>>>();
    // 3) output projection (1xTF32)
    gemm_tf32<2><<<dim3(HIDDEN / 128, MROWS / 128), blk, GEMM_SMEM>>>(
        nullptr, o_w, o_b, out, HIDDEN, HIDDEN);
}

// round 13
// speedup vs baseline: 3.2225x; 1.1126x over previous
#include <cuda_runtime.h>
#include <cstdint>

#define HIDDEN 1024
#define HEADS 16
#define HDIM 64
#define BATCH 2
#define SEQ 2048
#define MROWS (BATCH * SEQ)   // 4096

// ---------------- scratch (device globals; allocation-free) ----------------
__device__ float g_Q[(size_t)BATCH * HEADS * SEQ * HDIM];
__device__ float g_K[(size_t)BATCH * HEADS * SEQ * HDIM];
__device__ float g_V[(size_t)BATCH * HEADS * SEQ * HDIM];
__device__ float g_att[(size_t)BATCH * SEQ * HIDDEN];       // tf32-rounded by attn epilogue
// tf32-pre-rounded copies of the external inputs
__device__ float g_xr[(size_t)MROWS * HIDDEN];
__device__ float g_qkvwr[(size_t)3 * HIDDEN * HIDDEN];
__device__ float g_owr[(size_t)HIDDEN * HIDDEN];

// ---------------- helpers ---------------------------------------------------
__device__ __forceinline__ float tf32_rna(float x) {
    uint32_t u;
    asm("cvt.rna.tf32.f32 %0, %1;" : "=r"(u) : "f"(x));
    return __uint_as_float(u);
}

// D += A(16x8 tf32) * B(8x8 tf32), fp32 accumulate
__device__ __forceinline__ void mma8(float* d, const uint32_t* a, const uint32_t* b) {
    asm volatile(
        "mma.sync.aligned.m16n8k8.row.col.f32.tf32.tf32.f32 "
        "{%0,%1,%2,%3}, {%4,%5,%6,%7}, {%8,%9}, {%0,%1,%2,%3};\n"
        : "+f"(d[0]), "+f"(d[1]), "+f"(d[2]), "+f"(d[3])
        : "r"(a[0]), "r"(a[1]), "r"(a[2]), "r"(a[3]), "r"(b[0]), "r"(b[1]));
}

__device__ __forceinline__ void cp16(uint32_t smem_dst, const float* gmem_src) {
    asm volatile("cp.async.ca.shared.global [%0], [%1], 16;\n"
                 :: "r"(smem_dst), "l"(gmem_src));
}
__device__ __forceinline__ void cp_commit() {
    asm volatile("cp.async.commit_group;\n" ::: "memory");
}
__device__ __forceinline__ void cp_wait0() {
    asm volatile("cp.async.wait_group 0;\n" ::: "memory");
}

// ---------------- pre-round inputs to tf32 ----------------------------------
__global__ void round_pre(const float* __restrict__ x,
                          const float* __restrict__ w1,
                          const float* __restrict__ w2)
{
    const size_t NX  = (size_t)MROWS * HIDDEN / 4;       // float4 counts
    const size_t NW1 = (size_t)3 * HIDDEN * HIDDEN / 4;
    const size_t NW2 = (size_t)HIDDEN * HIDDEN / 4;
    size_t i0 = (size_t)blockIdx.x * blockDim.x + threadIdx.x;
    size_t st = (size_t)gridDim.x * blockDim.x;
    float4* dx = (float4*)g_xr;
    float4* d1 = (float4*)g_qkvwr;
    float4* d2 = (float4*)g_owr;
    for (size_t j = i0; j < NX; j += st) {
        float4 v = ((const float4*)x)[j];
        dx[j] = make_float4(tf32_rna(v.x), tf32_rna(v.y), tf32_rna(v.z), tf32_rna(v.w));
    }
    for (size_t j = i0; j < NW1; j += st) {
        float4 v = ((const float4*)w1)[j];
        d1[j] = make_float4(tf32_rna(v.x), tf32_rna(v.y), tf32_rna(v.z), tf32_rna(v.w));
    }
    for (size_t j = i0; j < NW2; j += st) {
        float4 v = ((const float4*)w2)[j];
        d2[j] = make_float4(tf32_rna(v.x), tf32_rna(v.y), tf32_rna(v.z), tf32_rna(v.w));
    }
}

// ---------------- 1xTF32 GEMM:  C[m,n] = sum_k A[m,k]*B[n,k] + bias[n] ------
// Inputs already tf32-rounded. cp.async double-buffered staging, no STS.
// MODE 1: A = g_xr,  B = g_qkvwr, epilogue scatters into g_Q/g_K/g_V
// MODE 2: A = g_att, B = g_owr,   epilogue writes plain row-major C
// CTA tile 128x128, BK=32, 256 threads = 8 warps (4m x 2n), warp tile 32x64.
#define GPAD 36
#define GBUF (2 * 128 * GPAD)                       // floats per buffer (A+B)
#define GEMM_SMEM (2 * GBUF * (int)sizeof(float))   // 73728 bytes

template <int MODE>
__global__ __launch_bounds__(256, 2) void gemm_tf32(
    const float* __restrict__ bias, float* __restrict__ C,
    int N, int K)
{
    extern __shared__ float sm[];

    const int tid  = threadIdx.x;
    const int lane = tid & 31, warp = tid >> 5;
    const int g = lane >> 2, tig = lane & 3;
    const int wm = (warp >> 1) * 32;    // warp row base
    const int wn = (warp & 1) * 64;     // warp col base

    const float* Ab = (MODE == 2 ? g_att : g_xr) + (size_t)blockIdx.y * 128 * K;
    const float* Bb = (MODE == 2 ? g_owr : g_qkvwr) + (size_t)blockIdx.x * 128 * K;

    const int r0 = tid >> 3;            // 0..31 -> rows r0, r0+32, r0+64, r0+96
    const int c0 = (tid & 7) << 2;      // 0,4,..28

    const uint32_t sbase = (uint32_t)__cvta_generic_to_shared(sm);

    float acc[2][8][4];
#pragma unroll
    for (int mt = 0; mt < 2; mt++)
#pragma unroll
        for (int nt = 0; nt < 8; nt++)
#pragma unroll
            for (int j = 0; j < 4; j++) acc[mt][nt][j] = 0.0f;

    // stage buffer 0 (async)
#pragma unroll
    for (int i = 0; i < 4; i++) {
        int row = r0 + i * 32;
        cp16(sbase + (uint32_t)(row * GPAD + c0) * 4, Ab + (size_t)row * K + c0);
        cp16(sbase + (uint32_t)(128 * GPAD + row * GPAD + c0) * 4, Bb + (size_t)row * K + c0);
    }
    cp_commit();

    const int NT = K / 32;
    for (int it = 0; it < NT; it++) {
        cp_wait0();        // this thread's stage of buf[it&1] landed
        __syncthreads();   // all threads' stages visible; all done reading buf[(it+1)&1]

        if (it + 1 < NT) {   // issue next tile async; lands under the MMA below
            int k0 = (it + 1) * 32;
            uint32_t bo = (uint32_t)(((it + 1) & 1) * GBUF);
#pragma unroll
            for (int i = 0; i < 4; i++) {
                int row = r0 + i * 32;
                cp16(sbase + (bo + row * GPAD + c0) * 4, Ab + (size_t)row * K + k0 + c0);
                cp16(sbase + (bo + 128 * GPAD + row * GPAD + c0) * 4,
                     Bb + (size_t)row * K + k0 + c0);
            }
            cp_commit();
        }

        const uint32_t* uA = (const uint32_t*)(sm + (it & 1) * GBUF);
        const uint32_t* uB = uA + 128 * GPAD;

#pragma unroll
        for (int ks = 0; ks < 4; ks++) {
            const int k0 = ks * 8;
            uint32_t ah[2][4];
#pragma unroll
            for (int mt = 0; mt < 2; mt++) {
                int base = (wm + mt * 16 + g) * GPAD + k0 + tig;
                ah[mt][0] = uA[base];
                ah[mt][1] = uA[base + 8 * GPAD];
                ah[mt][2] = uA[base + 4];
                ah[mt][3] = uA[base + 8 * GPAD + 4];
            }
#pragma unroll
            for (int nt = 0; nt < 8; nt++) {
                int base = (wn + nt * 8 + g) * GPAD + k0 + tig;
                uint32_t bh[2] = {uB[base], uB[base + 4]};
                mma8(acc[0][nt], ah[0], bh);
                mma8(acc[1][nt], ah[1], bh);
            }
        }
    }

    // epilogue
#pragma unroll
    for (int mt = 0; mt < 2; mt++) {
#pragma unroll
        for (int half = 0; half < 2; half++) {
            int m = blockIdx.y * 128 + wm + mt * 16 + g + half * 8;
#pragma unroll
            for (int nt = 0; nt < 8; nt++) {
                int n = blockIdx.x * 128 + wn + nt * 8 + 2 * tig;
                float v0 = acc[mt][nt][half * 2 + 0] + bias[n];
                float v1 = acc[mt][nt][half * 2 + 1] + bias[n + 1];
                if (MODE == 1) {
                    int b = m >> 11;            // SEQ = 2048
                    int s = m & (SEQ - 1);
                    int h = n / 192;
                    int jj = n - h * 192;
                    float* dst = (jj < 64) ? g_Q : (jj < 128 ? g_K : g_V);
                    size_t idx = ((((size_t)b * HEADS + h) * SEQ + s) << 6) + (jj & 63);
                    *(float2*)(dst + idx) = make_float2(v0, v1);
                } else {
                    *(float2*)(C + (size_t)m * N + n) = make_float2(v0, v1);
                }
            }
        }
    }
}

// ---------------- flash attention, TF32 mma (online softmax) ----------------
// One CTA per (b, h, 256-row query block). 512 thr = 16 warps; warp owns 16
// query rows. Key blocks of 64, double-buffered K/V (one syncthreads/block).
#define APAD 68
#define AKV (64 * APAD)
#define ATTN_SMEM ((256 + 2 * 64 + 2 * 64 + 256) * APAD * (int)sizeof(float)) // 208896

__global__ __launch_bounds__(512, 1) void attn_tf32()
{
    extern __shared__ float sm[];
    float* Qs = sm;                         // [256][APAD]  (tf32, pre-scaled)
    float* Ks = sm + 256 * APAD;            // 2 x [64][APAD] key-major
    float* Vs = Ks + 2 * AKV;               // 2 x [64][APAD] key-major
    float* Ps = Vs + 2 * AKV;               // [256][APAD]  row-major P
    const uint32_t* uQ = (const uint32_t*)Qs;
    const uint32_t* uP = (const uint32_t*)Ps;

    const int tid  = threadIdx.x;
    const int lane = tid & 31, warp = tid >> 5;   // 0..15
    const int g = lane >> 2, tig = lane & 3;
    const int wq = warp * 16;               // warp's query-row base (0..240)

    const int qb = blockIdx.x, h = blockIdx.y, b = blockIdx.z;
    const size_t headBase = ((size_t)b * HEADS + h) * SEQ * HDIM;
    const float* Qg = g_Q + headBase + (size_t)qb * 256 * HDIM;
    const float* Kg = g_K + headBase;
    const float* Vg = g_V + headBase;

    // stage Q once: scale by 1/sqrt(64)=0.125, round to tf32
    {
        int r = tid >> 4, c = (tid & 15) << 2;   // r 0..31, c 0..60
#pragma unroll
        for (int i = 0; i < 8; i++) {
            int row = r + i * 32;
            float4 v = *(const float4*)(Qg + (size_t)row * HDIM + c);
            *(float4*)(Qs + row * APAD + c) =
                make_float4(tf32_rna(v.x * 0.125f), tf32_rna(v.y * 0.125f),
                            tf32_rna(v.z * 0.125f), tf32_rna(v.w * 0.125f));
        }
    }

    float m_i[2] = {-3.0e38f, -3.0e38f};
    float l_i[2] = {0.0f, 0.0f};
    float o[8][4];
#pragma unroll
    for (int nt = 0; nt < 8; nt++)
#pragma unroll
        for (int j = 0; j < 4; j++) o[nt][j] = 0.0f;

    const int kr = tid >> 4, kc = (tid & 15) << 2;   // kr 0..31
    // stage K/V buffer 0 (rows kr, kr+32)
#pragma unroll
    for (int i = 0; i < 2; i++) {
        int row = kr + i * 32;
        float4 v = *(const float4*)(Kg + (size_t)row * HDIM + kc);
        *(float4*)(Ks + row * APAD + kc) =
            make_float4(tf32_rna(v.x), tf32_rna(v.y), tf32_rna(v.z), tf32_rna(v.w));
        v = *(const float4*)(Vg + (size_t)row * HDIM + kc);
        *(float4*)(Vs + row * APAD + kc) =
            make_float4(tf32_rna(v.x), tf32_rna(v.y), tf32_rna(v.z), tf32_rna(v.w));
    }

    const int NB = SEQ / 64;
    for (int kb = 0; kb < NB; kb++) {
        __syncthreads();   // buf[kb&1] staged; reads of buf[(kb+1)&1] (iter kb-1) done
        const uint32_t* uK = (const uint32_t*)(Ks + (kb & 1) * AKV);
        const uint32_t* uV = (const uint32_t*)(Vs + (kb & 1) * AKV);

        // ---- S = Q K^T (16 rows x 64 keys per warp) ----
        float s[8][4];
#pragma unroll
        for (int nt = 0; nt < 8; nt++)
#pragma unroll
            for (int j = 0; j < 4; j++) s[nt][j] = 0.0f;

#pragma unroll
        for (int ks = 0; ks < 8; ks++) {
            const int k0 = ks * 8;
            uint32_t qa[4];
            int base = (wq + g) * APAD + k0 + tig;
            qa[0] = uQ[base];
            qa[1] = uQ[base + 8 * APAD];
            qa[2] = uQ[base + 4];
            qa[3] = uQ[base + 8 * APAD + 4];
#pragma unroll
            for (int nt = 0; nt < 8; nt++) {
                int bb = (nt * 8 + g) * APAD + k0 + tig;
                uint32_t kf[2] = {uK[bb], uK[bb + 4]};
                mma8(s[nt], qa, kf);
            }
        }

        // ---- online softmax (rows wq+g and wq+g+8) ----
#pragma unroll
        for (int half = 0; half < 2; half++) {
            float rmax = -3.0e38f;
#pragma unroll
            for (int nt = 0; nt < 8; nt++)
                rmax = fmaxf(rmax, fmaxf(s[nt][half * 2], s[nt][half * 2 + 1]));
            rmax = fmaxf(rmax, __shfl_xor_sync(0xffffffffu, rmax, 1));
            rmax = fmaxf(rmax, __shfl_xor_sync(0xffffffffu, rmax, 2));
            float mnew  = fmaxf(m_i[half], rmax);
            float alpha = __expf(m_i[half] - mnew);
            m_i[half] = mnew;
            float rs = 0.0f;
            int prow = (wq + g + half * 8) * APAD + 2 * tig;
#pragma unroll
            for (int nt = 0; nt < 8; nt++) {
                float p0 = __expf(s[nt][half * 2] - mnew);
                float p1 = __expf(s[nt][half * 2 + 1] - mnew);
                rs += p0 + p1;
                *(float2*)(Ps + prow + nt * 8) = make_float2(tf32_rna(p0), tf32_rna(p1));
                o[nt][half * 2]     *= alpha;
                o[nt][half * 2 + 1] *= alpha;
            }
            rs += __shfl_xor_sync(0xffffffffu, rs, 1);
            rs += __shfl_xor_sync(0xffffffffu, rs, 2);
            l_i[half] = l_i[half] * alpha + rs;
        }
        __syncwarp();   // Ps rows are warp-private; make stores visible

        if (kb + 1 < NB) {   // stage next K/V into the other buffer
            const float* Kn = Kg + (size_t)(kb + 1) * 64 * HDIM;
            const float* Vn = Vg + (size_t)(kb + 1) * 64 * HDIM;
            float* Kd = Ks + ((kb + 1) & 1) * AKV;
            float* Vd = Vs + ((kb + 1) & 1) * AKV;
#pragma unroll
            for (int i = 0; i < 2; i++) {
                int row = kr + i * 32;
                float4 v = *(const float4*)(Kn + (size_t)row * HDIM + kc);
                *(float4*)(Kd + row * APAD + kc) =
                    make_float4(tf32_rna(v.x), tf32_rna(v.y), tf32_rna(v.z), tf32_rna(v.w));
                v = *(const float4*)(Vn + (size_t)row * HDIM + kc);
                *(float4*)(Vd + row * APAD + kc) =
                    make_float4(tf32_rna(v.x), tf32_rna(v.y), tf32_rna(v.z), tf32_rna(v.w));
            }
        }

        // ---- O += P V ----
#pragma unroll
        for (int ks = 0; ks < 8; ks++) {
            const int k0 = ks * 8;
            uint32_t pa[4];
            int base = (wq + g) * APAD + k0 + tig;
            pa[0] = uP[base];
            pa[1] = uP[base + 8 * APAD];
            pa[2] = uP[base + 4];
            pa[3] = uP[base + 8 * APAD + 4];
#pragma unroll
            for (int nt = 0; nt < 8; nt++) {
                uint32_t vf[2] = {uV[(k0 + tig) * APAD + nt * 8 + g],
                                  uV[(k0 + tig + 4) * APAD + nt * 8 + g]};
                mma8(o[nt], pa, vf);
            }
        }
    }

    // ---- epilogue: normalize, round to tf32 (gemm2 reads raw), write -------
    float* ob = g_att + ((size_t)b * SEQ + (size_t)qb * 256) * HIDDEN + h * HDIM;
#pragma unroll
    for (int half = 0; half < 2; half++) {
        float inv = 1.0f / l_i[half];
        int row = wq + g + half * 8;
#pragma unroll
        for (int nt = 0; nt < 8; nt++)
            *(float2*)(ob + (size_t)row * HIDDEN + nt * 8 + 2 * tig) =
                make_float2(tf32_rna(o[nt][half * 2] * inv),
                            tf32_rna(o[nt][half * 2 + 1] * inv));
    }
}

// ---------------- launch ---------------------------------------------------
extern "C" void kernel_launch(void* const* d_in, const int* in_sizes, int n_in,
                              void* d_out, int out_size)
{
    const float* x     = (const float*)d_in[0];
    const float* qkv_w = (const float*)d_in[1];
    const float* qkv_b = (const float*)d_in[2];
    const float* o_w   = (const float*)d_in[3];
    const float* o_b   = (const float*)d_in[4];
    float* out = (float*)d_out;

    cudaFuncSetAttribute(gemm_tf32<1>, cudaFuncAttributeMaxDynamicSharedMemorySize, GEMM_SMEM);
    cudaFuncSetAttribute(gemm_tf32<2>, cudaFuncAttributeMaxDynamicSharedMemorySize, GEMM_SMEM);
    cudaFuncSetAttribute(attn_tf32,   cudaFuncAttributeMaxDynamicSharedMemorySize, ATTN_SMEM);

    // 0) round inputs to tf32 once
    round_pre<<<592, 256>>>(x, qkv_w, o_w);
    // 1) QKV projection (1xTF32, cp.async) + scatter to [b,h,s,d]
    gemm_tf32<1><<<dim3(3 * HIDDEN / 128, MROWS / 128), dim3(256), GEMM_SMEM>>>(
        qkv_b, nullptr, 3 * HIDDEN, HIDDEN);
    // 2) attention (1xTF32, 256-row query blocks, 16 warps)
    attn_tf32<<<dim3(SEQ / 256, HEADS, BATCH), dim3(512), ATTN_SMEM>>>();
    // 3) output projection (1xTF32, cp.async)
    gemm_tf32<2><<<dim3(HIDDEN / 128, MROWS / 128), dim3(256), GEMM_SMEM>>>(
        o_b, out, HIDDEN, HIDDEN);
}

// round 14
// speedup vs baseline: 3.7765x; 1.1719x over previous
#include <cuda_runtime.h>
#include <cstdint>

#define HIDDEN 1024
#define HEADS 16
#define HDIM 64
#define BATCH 2
#define SEQ 2048
#define MROWS (BATCH * SEQ)   // 4096

// ---------------- scratch (device globals; allocation-free) ----------------
__device__ float g_Q[(size_t)BATCH * HEADS * SEQ * HDIM];   // raw fp32
__device__ float g_K[(size_t)BATCH * HEADS * SEQ * HDIM];   // tf32-rounded
__device__ float g_V[(size_t)BATCH * HEADS * SEQ * HDIM];   // tf32-rounded
__device__ float g_att[(size_t)BATCH * SEQ * HIDDEN];       // tf32-rounded
// tf32-pre-rounded copies of the external inputs
__device__ float g_xr[(size_t)MROWS * HIDDEN];
__device__ float g_qkvwr[(size_t)3 * HIDDEN * HIDDEN];
__device__ float g_owr[(size_t)HIDDEN * HIDDEN];

// ---------------- helpers ---------------------------------------------------
__device__ __forceinline__ float tf32_rna(float x) {
    uint32_t u;
    asm("cvt.rna.tf32.f32 %0, %1;" : "=r"(u) : "f"(x));
    return __uint_as_float(u);
}
__device__ __forceinline__ float ex2(float x) {
    float r;
    asm("ex2.approx.ftz.f32 %0, %1;" : "=f"(r) : "f"(x));
    return r;
}

// D += A(16x8 tf32) * B(8x8 tf32), fp32 accumulate
__device__ __forceinline__ void mma8(float* d, const uint32_t* a, const uint32_t* b) {
    asm volatile(
        "mma.sync.aligned.m16n8k8.row.col.f32.tf32.tf32.f32 "
        "{%0,%1,%2,%3}, {%4,%5,%6,%7}, {%8,%9}, {%0,%1,%2,%3};\n"
        : "+f"(d[0]), "+f"(d[1]), "+f"(d[2]), "+f"(d[3])
        : "r"(a[0]), "r"(a[1]), "r"(a[2]), "r"(a[3]), "r"(b[0]), "r"(b[1]));
}

__device__ __forceinline__ void cp16(uint32_t smem_dst, const float* gmem_src) {
    asm volatile("cp.async.ca.shared.global [%0], [%1], 16;\n"
                 :: "r"(smem_dst), "l"(gmem_src));
}
__device__ __forceinline__ void cp_commit() {
    asm volatile("cp.async.commit_group;\n" ::: "memory");
}
__device__ __forceinline__ void cp_wait0() {
    asm volatile("cp.async.wait_group 0;\n" ::: "memory");
}

// ---------------- pre-round inputs to tf32 ----------------------------------
__global__ void round_pre(const float* __restrict__ x,
                          const float* __restrict__ w1,
                          const float* __restrict__ w2)
{
    const size_t NX  = (size_t)MROWS * HIDDEN / 4;       // float4 counts
    const size_t NW1 = (size_t)3 * HIDDEN * HIDDEN / 4;
    const size_t NW2 = (size_t)HIDDEN * HIDDEN / 4;
    size_t i0 = (size_t)blockIdx.x * blockDim.x + threadIdx.x;
    size_t st = (size_t)gridDim.x * blockDim.x;
    float4* dx = (float4*)g_xr;
    float4* d1 = (float4*)g_qkvwr;
    float4* d2 = (float4*)g_owr;
    for (size_t j = i0; j < NX; j += st) {
        float4 v = ((const float4*)x)[j];
        dx[j] = make_float4(tf32_rna(v.x), tf32_rna(v.y), tf32_rna(v.z), tf32_rna(v.w));
    }
    for (size_t j = i0; j < NW1; j += st) {
        float4 v = ((const float4*)w1)[j];
        d1[j] = make_float4(tf32_rna(v.x), tf32_rna(v.y), tf32_rna(v.z), tf32_rna(v.w));
    }
    for (size_t j = i0; j < NW2; j += st) {
        float4 v = ((const float4*)w2)[j];
        d2[j] = make_float4(tf32_rna(v.x), tf32_rna(v.y), tf32_rna(v.z), tf32_rna(v.w));
    }
}

// ---------------- 1xTF32 GEMM:  C[m,n] = sum_k A[m,k]*B[n,k] + bias[n] ------
// Inputs already tf32-rounded. cp.async double-buffered staging, no STS.
// MODE 1: A = g_xr,  B = g_qkvwr, epilogue scatters Q (raw) / K,V (tf32-rna)
// MODE 2: A = g_att, B = g_owr,   epilogue writes plain row-major C
// CTA tile 128x128, BK=32, 256 threads = 8 warps (4m x 2n), warp tile 32x64.
#define GPAD 36
#define GBUF (2 * 128 * GPAD)                       // floats per buffer (A+B)
#define GEMM_SMEM (2 * GBUF * (int)sizeof(float))   // 73728 bytes

template <int MODE>
__global__ __launch_bounds__(256, 2) void gemm_tf32(
    const float* __restrict__ bias, float* __restrict__ C,
    int N, int K)
{
    extern __shared__ float sm[];

    const int tid  = threadIdx.x;
    const int lane = tid & 31, warp = tid >> 5;
    const int g = lane >> 2, tig = lane & 3;
    const int wm = (warp >> 1) * 32;    // warp row base
    const int wn = (warp & 1) * 64;     // warp col base

    const float* Ab = (MODE == 2 ? g_att : g_xr) + (size_t)blockIdx.y * 128 * K;
    const float* Bb = (MODE == 2 ? g_owr : g_qkvwr) + (size_t)blockIdx.x * 128 * K;

    const int r0 = tid >> 3;            // 0..31 -> rows r0, r0+32, r0+64, r0+96
    const int c0 = (tid & 7) << 2;      // 0,4,..28

    const uint32_t sbase = (uint32_t)__cvta_generic_to_shared(sm);

    float acc[2][8][4];
#pragma unroll
    for (int mt = 0; mt < 2; mt++)
#pragma unroll
        for (int nt = 0; nt < 8; nt++)
#pragma unroll
            for (int j = 0; j < 4; j++) acc[mt][nt][j] = 0.0f;

    // stage buffer 0 (async)
#pragma unroll
    for (int i = 0; i < 4; i++) {
        int row = r0 + i * 32;
        cp16(sbase + (uint32_t)(row * GPAD + c0) * 4, Ab + (size_t)row * K + c0);
        cp16(sbase + (uint32_t)(128 * GPAD + row * GPAD + c0) * 4, Bb + (size_t)row * K + c0);
    }
    cp_commit();

    const int NT = K / 32;
    for (int it = 0; it < NT; it++) {
        cp_wait0();        // this thread's stage of buf[it&1] landed
        __syncthreads();   // all threads' stages visible; all done reading buf[(it+1)&1]

        if (it + 1 < NT) {   // issue next tile async; lands under the MMA below
            int k0 = (it + 1) * 32;
            uint32_t bo = (uint32_t)(((it + 1) & 1) * GBUF);
#pragma unroll
            for (int i = 0; i < 4; i++) {
                int row = r0 + i * 32;
                cp16(sbase + (bo + row * GPAD + c0) * 4, Ab + (size_t)row * K + k0 + c0);
                cp16(sbase + (bo + 128 * GPAD + row * GPAD + c0) * 4,
                     Bb + (size_t)row * K + k0 + c0);
            }
            cp_commit();
        }

        const uint32_t* uA = (const uint32_t*)(sm + (it & 1) * GBUF);
        const uint32_t* uB = uA + 128 * GPAD;

#pragma unroll
        for (int ks = 0; ks < 4; ks++) {
            const int k0 = ks * 8;
            uint32_t ah[2][4];
#pragma unroll
            for (int mt = 0; mt < 2; mt++) {
                int base = (wm + mt * 16 + g) * GPAD + k0 + tig;
                ah[mt][0] = uA[base];
                ah[mt][1] = uA[base + 8 * GPAD];
                ah[mt][2] = uA[base + 4];
                ah[mt][3] = uA[base + 8 * GPAD + 4];
            }
#pragma unroll
            for (int nt = 0; nt < 8; nt++) {
                int base = (wn + nt * 8 + g) * GPAD + k0 + tig;
                uint32_t bh[2] = {uB[base], uB[base + 4]};
                mma8(acc[0][nt], ah[0], bh);
                mma8(acc[1][nt], ah[1], bh);
            }
        }
    }

    // epilogue
#pragma unroll
    for (int mt = 0; mt < 2; mt++) {
#pragma unroll
        for (int half = 0; half < 2; half++) {
            int m = blockIdx.y * 128 + wm + mt * 16 + g + half * 8;
#pragma unroll
            for (int nt = 0; nt < 8; nt++) {
                int n = blockIdx.x * 128 + wn + nt * 8 + 2 * tig;
                float v0 = acc[mt][nt][half * 2 + 0] + bias[n];
                float v1 = acc[mt][nt][half * 2 + 1] + bias[n + 1];
                if (MODE == 1) {
                    int b = m >> 11;            // SEQ = 2048
                    int s = m & (SEQ - 1);
                    int h = n / 192;
                    int jj = n - h * 192;
                    float* dst;
                    if (jj < 64) {
                        dst = g_Q;               // raw; attn scales+rounds
                    } else {
                        dst = (jj < 128) ? g_K : g_V;
                        v0 = tf32_rna(v0);       // pre-round so attn can cp.async
                        v1 = tf32_rna(v1);
                    }
                    size_t idx = ((((size_t)b * HEADS + h) * SEQ + s) << 6) + (jj & 63);
                    *(float2*)(dst + idx) = make_float2(v0, v1);
                } else {
                    *(float2*)(C + (size_t)m * N + n) = make_float2(v0, v1);
                }
            }
        }
    }
}

// ---------------- flash attention, TF32 mma (online softmax) ----------------
// One CTA per (b, h, 256-row query block). 256 thr = 8 warps; warp owns 32
// query rows (mt=2) x 64 keys -> B-fragments amortize over 2 A-tiles.
// K/V already tf32-rounded in gmem -> staged with cp.async (double-buffered).
// Softmax in log2 domain (Q pre-scaled by 0.125*log2e).
#define APAD 68
#define AKV (64 * APAD)
#define ATTN_SMEM ((256 + 2 * 64 + 2 * 64 + 256) * APAD * (int)sizeof(float)) // 208896
#define QSC 0.18033688011112042f   // 0.125 * log2(e)

__global__ __launch_bounds__(256, 1) void attn_tf32()
{
    extern __shared__ float sm[];
    float* Qs = sm;                         // [256][APAD]  (tf32, pre-scaled)
    float* Ks = sm + 256 * APAD;            // 2 x [64][APAD] key-major
    float* Vs = Ks + 2 * AKV;               // 2 x [64][APAD] key-major
    float* Ps = Vs + 2 * AKV;               // [256][APAD]  row-major P
    const uint32_t* uQ = (const uint32_t*)Qs;
    const uint32_t* uP = (const uint32_t*)Ps;
    const uint32_t sbase = (uint32_t)__cvta_generic_to_shared(sm);
    const uint32_t sK0 = sbase + 256 * APAD * 4;
    const uint32_t sV0 = sK0 + 2 * AKV * 4;

    const int tid  = threadIdx.x;
    const int lane = tid & 31, warp = tid >> 5;   // 0..7
    const int g = lane >> 2, tig = lane & 3;
    const int wq = warp * 32;               // warp's query-row base (0..224)

    const int qb = blockIdx.x, h = blockIdx.y, b = blockIdx.z;
    const size_t headBase = ((size_t)b * HEADS + h) * SEQ * HDIM;
    const float* Qg = g_Q + headBase + (size_t)qb * 256 * HDIM;
    const float* Kg = g_K + headBase;
    const float* Vg = g_V + headBase;

    // stage K/V block 0 via cp.async (data already tf32-rounded)
#pragma unroll
    for (int t = 0; t < 4; t++) {
        int slot = tid + t * 256;            // 0..1023
        int row = slot >> 4, c = (slot & 15) << 2;
        cp16(sK0 + (uint32_t)(row * APAD + c) * 4, Kg + (size_t)row * HDIM + c);
        cp16(sV0 + (uint32_t)(row * APAD + c) * 4, Vg + (size_t)row * HDIM + c);
    }
    cp_commit();

    // stage Q once: scale by 0.125*log2e, round to tf32
    {
        int r = tid >> 4, c = (tid & 15) << 2;   // r 0..15, c 0..60
#pragma unroll
        for (int i = 0; i < 16; i++) {
            int row = r + i * 16;
            float4 v = *(const float4*)(Qg + (size_t)row * HDIM + c);
            *(float4*)(Qs + row * APAD + c) =
                make_float4(tf32_rna(v.x * QSC), tf32_rna(v.y * QSC),
                            tf32_rna(v.z * QSC), tf32_rna(v.w * QSC));
        }
    }

    float m_i[2][2], l_i[2][2];
    float o[2][8][4];
#pragma unroll
    for (int mt = 0; mt < 2; mt++) {
#pragma unroll
        for (int half = 0; half < 2; half++) { m_i[mt][half] = -3.0e38f; l_i[mt][half] = 0.0f; }
#pragma unroll
        for (int nt = 0; nt < 8; nt++)
#pragma unroll
            for (int j = 0; j < 4; j++) o[mt][nt][j] = 0.0f;
    }

    const int NB = SEQ / 64;
    for (int kb = 0; kb < NB; kb++) {
        cp_wait0();
        __syncthreads();   // buf[kb&1] staged; reads of buf[(kb+1)&1] (iter kb-1) done
        const uint32_t* uK = (const uint32_t*)(Ks + (kb & 1) * AKV);
        const uint32_t* uV = (const uint32_t*)(Vs + (kb & 1) * AKV);

        if (kb + 1 < NB) {   // issue next K/V block async into the other buffer
            const float* Kn = Kg + (size_t)(kb + 1) * 64 * HDIM;
            const float* Vn = Vg + (size_t)(kb + 1) * 64 * HDIM;
            uint32_t bo = (uint32_t)(((kb + 1) & 1) * AKV) * 4;
#pragma unroll
            for (int t = 0; t < 4; t++) {
                int slot = tid + t * 256;
                int row = slot >> 4, c = (slot & 15) << 2;
                cp16(sK0 + bo + (uint32_t)(row * APAD + c) * 4, Kn + (size_t)row * HDIM + c);
                cp16(sV0 + bo + (uint32_t)(row * APAD + c) * 4, Vn + (size_t)row * HDIM + c);
            }
            cp_commit();
        }

        // ---- S = Q K^T (32 rows x 64 keys per warp, log2-scaled) ----
        float s[2][8][4];
#pragma unroll
        for (int mt = 0; mt < 2; mt++)
#pragma unroll
            for (int nt = 0; nt < 8; nt++)
#pragma unroll
                for (int j = 0; j < 4; j++) s[mt][nt][j] = 0.0f;

#pragma unroll
        for (int ks = 0; ks < 8; ks++) {
            const int k0 = ks * 8;
            uint32_t qa[2][4];
#pragma unroll
            for (int mt = 0; mt < 2; mt++) {
                int base = (wq + mt * 16 + g) * APAD + k0 + tig;
                qa[mt][0] = uQ[base];
                qa[mt][1] = uQ[base + 8 * APAD];
                qa[mt][2] = uQ[base + 4];
                qa[mt][3] = uQ[base + 8 * APAD + 4];
            }
#pragma unroll
            for (int nt = 0; nt < 8; nt++) {
                int bb = (nt * 8 + g) * APAD + k0 + tig;
                uint32_t kf[2] = {uK[bb], uK[bb + 4]};
                mma8(s[0][nt], qa[0], kf);
                mma8(s[1][nt], qa[1], kf);
            }
        }

        // ---- online softmax (log2 domain) ----
#pragma unroll
        for (int mt = 0; mt < 2; mt++) {
#pragma unroll
            for (int half = 0; half < 2; half++) {
                float rmax = -3.0e38f;
#pragma unroll
                for (int nt = 0; nt < 8; nt++)
                    rmax = fmaxf(rmax, fmaxf(s[mt][nt][half * 2], s[mt][nt][half * 2 + 1]));
                rmax = fmaxf(rmax, __shfl_xor_sync(0xffffffffu, rmax, 1));
                rmax = fmaxf(rmax, __shfl_xor_sync(0xffffffffu, rmax, 2));
                float mnew  = fmaxf(m_i[mt][half], rmax);
                float alpha = ex2(m_i[mt][half] - mnew);
                m_i[mt][half] = mnew;
                float rs = 0.0f;
                int prow = (wq + mt * 16 + g + half * 8) * APAD + 2 * tig;
#pragma unroll
                for (int nt = 0; nt < 8; nt++) {
                    float p0 = ex2(s[mt][nt][half * 2] - mnew);
                    float p1 = ex2(s[mt][nt][half * 2 + 1] - mnew);
                    rs += p0 + p1;
                    *(float2*)(Ps + prow + nt * 8) = make_float2(tf32_rna(p0), tf32_rna(p1));
                    o[mt][nt][half * 2]     *= alpha;
                    o[mt][nt][half * 2 + 1] *= alpha;
                }
                rs += __shfl_xor_sync(0xffffffffu, rs, 1);
                rs += __shfl_xor_sync(0xffffffffu, rs, 2);
                l_i[mt][half] = l_i[mt][half] * alpha + rs;
            }
        }
        __syncwarp();   // Ps rows are warp-private; make stores visible

        // ---- O += P V ----
#pragma unroll
        for (int ks = 0; ks < 8; ks++) {
            const int k0 = ks * 8;
            uint32_t pa[2][4];
#pragma unroll
            for (int mt = 0; mt < 2; mt++) {
                int base = (wq + mt * 16 + g) * APAD + k0 + tig;
                pa[mt][0] = uP[base];
                pa[mt][1] = uP[base + 8 * APAD];
                pa[mt][2] = uP[base + 4];
                pa[mt][3] = uP[base + 8 * APAD + 4];
            }
#pragma unroll
            for (int nt = 0; nt < 8; nt++) {
                uint32_t vf[2] = {uV[(k0 + tig) * APAD + nt * 8 + g],
                                  uV[(k0 + tig + 4) * APAD + nt * 8 + g]};
                mma8(o[0][nt], pa[0], vf);
                mma8(o[1][nt], pa[1], vf);
            }
        }
    }

    // ---- epilogue: normalize, round to tf32 (gemm2 reads raw), write -------
    float* ob = g_att + ((size_t)b * SEQ + (size_t)qb * 256) * HIDDEN + h * HDIM;
#pragma unroll
    for (int mt = 0; mt < 2; mt++) {
#pragma unroll
        for (int half = 0; half < 2; half++) {
            float inv = 1.0f / l_i[mt][half];
            int row = wq + mt * 16 + g + half * 8;
#pragma unroll
            for (int nt = 0; nt < 8; nt++)
                *(float2*)(ob + (size_t)row * HIDDEN + nt * 8 + 2 * tig) =
                    make_float2(tf32_rna(o[mt][nt][half * 2] * inv),
                                tf32_rna(o[mt][nt][half * 2 + 1] * inv));
        }
    }
}

// ---------------- launch ---------------------------------------------------
extern "C" void kernel_launch(void* const* d_in, const int* in_sizes, int n_in,
                              void* d_out, int out_size)
{
    const float* x     = (const float*)d_in[0];
    const float* qkv_w = (const float*)d_in[1];
    const float* qkv_b = (const float*)d_in[2];
    const float* o_w   = (const float*)d_in[3];
    const float* o_b   = (const float*)d_in[4];
    float* out = (float*)d_out;

    cudaFuncSetAttribute(gemm_tf32<1>, cudaFuncAttributeMaxDynamicSharedMemorySize, GEMM_SMEM);
    cudaFuncSetAttribute(gemm_tf32<2>, cudaFuncAttributeMaxDynamicSharedMemorySize, GEMM_SMEM);
    cudaFuncSetAttribute(attn_tf32,   cudaFuncAttributeMaxDynamicSharedMemorySize, ATTN_SMEM);

    // 0) round inputs to tf32 once
    round_pre<<<592, 256>>>(x, qkv_w, o_w);
    // 1) QKV projection (1xTF32, cp.async) + scatter; K/V pre-rounded
    gemm_tf32<1><<<dim3(3 * HIDDEN / 128, MROWS / 128), dim3(256), GEMM_SMEM>>>(
        qkv_b, nullptr, 3 * HIDDEN, HIDDEN);
    // 2) attention (1xTF32, 32 q-rows/warp, cp.async K/V)
    attn_tf32<<<dim3(SEQ / 256, HEADS, BATCH), dim3(256), ATTN_SMEM>>>();
    // 3) output projection (1xTF32, cp.async)
    gemm_tf32<2><<<dim3(HIDDEN / 128, MROWS / 128), dim3(256), GEMM_SMEM>>>(
        o_b, out, HIDDEN, HIDDEN);
}